// round 4
// baseline (speedup 1.0000x reference)
#include <cuda_runtime.h>
#include <math.h>

#define NMAX 100000
#define INC 64
#define HIDC 128
#define OUTC 64

typedef unsigned long long ull;

// Scratch (device globals — no allocation allowed)
__device__ __align__(256) float g_agg1[NMAX * INC];    // 25.6 MB
__device__ __align__(256) float g_h[NMAX * HIDC];      // 51.2 MB
__device__ __align__(256) float g_z[NMAX * OUTC];      // 25.6 MB  z = h @ W2l^T
__device__ __align__(256) float g_zagg[NMAX * OUTC];   // 25.6 MB  scattered z
__device__ __align__(256) float g_deg[NMAX];
// Transposed weights (filled by k_prep each call)
__device__ __align__(256) float g_Wcat[HIDC * HIDC];   // [k][o]: k<64->W1l, k>=64->W1r
__device__ __align__(256) float g_W2lT[HIDC * OUTC];   // [k][o]
__device__ __align__(256) float g_W2rT[HIDC * OUTC];   // [k][o]

// ---------------- packed f32x2 helpers ----------------
__device__ __forceinline__ void fma2(ull& d, ull a, ull b) {
    asm("fma.rn.f32x2 %0, %1, %2, %0;" : "+l"(d) : "l"(a), "l"(b));
}
__device__ __forceinline__ ull pack2(float x) {
    ull r; asm("mov.b64 %0, {%1, %1};" : "=l"(r) : "f"(x)); return r;
}
__device__ __forceinline__ float2 unpack2(ull v) {
    float2 r; asm("mov.b64 {%0, %1}, %2;" : "=f"(r.x), "=f"(r.y) : "l"(v)); return r;
}

// ---------------------------------------------------------------------------
// k_prep: transposed weight copies (coalesced smem fills in the GEMMs)
// ---------------------------------------------------------------------------
__global__ void k_prep(const float* __restrict__ W1l, const float* __restrict__ W1r,
                       const float* __restrict__ W2l, const float* __restrict__ W2r) {
    int stride = gridDim.x * blockDim.x;
    int tid = blockIdx.x * blockDim.x + threadIdx.x;
    for (int i = tid; i < HIDC * HIDC; i += stride) {
        int k = i >> 7, o = i & 127;
        g_Wcat[i] = (k < 64) ? W1l[o * 64 + k] : W1r[o * 64 + (k - 64)];
    }
    for (int i = tid; i < HIDC * OUTC; i += stride) {
        int k = i >> 6, o = i & 63;
        g_W2lT[i] = W2l[o * 128 + k];
        g_W2rT[i] = W2r[o * 128 + k];
    }
}

// ---------------------------------------------------------------------------
// k_zero: clear agg1, zagg, deg
// ---------------------------------------------------------------------------
__global__ void k_zero(int n) {
    long t1 = (long)n * (INC / 4);
    long t2 = t1 + (long)n * (OUTC / 4);
    long total = t2 + (n + 3) / 4;
    float4 z = make_float4(0.f, 0.f, 0.f, 0.f);
    for (long i = (long)blockIdx.x * blockDim.x + threadIdx.x; i < total;
         i += (long)gridDim.x * blockDim.x) {
        if (i < t1)       ((float4*)g_agg1)[i] = z;
        else if (i < t2)  ((float4*)g_zagg)[i - t1] = z;
        else              ((float4*)g_deg)[i - t2] = z;
    }
}

__device__ __forceinline__ void red_add_v4(float* addr, float4 v) {
    asm volatile("red.global.add.v4.f32 [%0], {%1,%2,%3,%4};"
                 :: "l"(addr), "f"(v.x), "f"(v.y), "f"(v.z), "f"(v.w)
                 : "memory");
}

// ---------------------------------------------------------------------------
// k_scatter1: agg1[dst] += x[src]  (8 threads/edge, 2 float4 each) + deg
// ---------------------------------------------------------------------------
__global__ void __launch_bounds__(256) k_scatter1(
    const float4* __restrict__ x4, const int* __restrict__ src,
    const int* __restrict__ dst, int E) {
    long idx = (long)blockIdx.x * blockDim.x + threadIdx.x;
    long total = (long)E * 8;
    if (idx >= total) return;
    int e = (int)(idx >> 3);
    int p = (int)(idx & 7);
    int s = src[e];
    int d = dst[e];
    float4 v0 = x4[(long)s * 16 + p * 2];
    float4 v1 = x4[(long)s * 16 + p * 2 + 1];
    red_add_v4(g_agg1 + (long)d * INC + p * 8, v0);
    red_add_v4(g_agg1 + (long)d * INC + p * 8 + 4, v1);
    if (p == 0) atomicAdd(g_deg + d, 1.0f);
}

// ---------------------------------------------------------------------------
// k_scatter2: zagg[dst] += z[src]  (8 threads/edge, 2 float4 each)
// ---------------------------------------------------------------------------
__global__ void __launch_bounds__(256) k_scatter2(
    const int* __restrict__ src, const int* __restrict__ dst, int E) {
    long idx = (long)blockIdx.x * blockDim.x + threadIdx.x;
    long total = (long)E * 8;
    if (idx >= total) return;
    int e = (int)(idx >> 3);
    int p = (int)(idx & 7);
    int s = src[e];
    int d = dst[e];
    const float4* z4 = (const float4*)g_z;
    float4 v0 = z4[(long)s * 16 + p * 2];
    float4 v1 = z4[(long)s * 16 + p * 2 + 1];
    red_add_v4(g_zagg + (long)d * OUTC + p * 8, v0);
    red_add_v4(g_zagg + (long)d * OUTC + p * 8 + 4, v1);
}

// ---------------------------------------------------------------------------
// k_mlp1 (512 threads, 64-node tile):
//   a = [inv*agg1 , x]  (K=128)  -> AH duplicated: AH[k][2m]=AH[k][2m+1]=a
//   h = relu(a @ Wcat + b1)      -> g_h, and AH re-filled with dup'd h
//   z = h @ W2l^T                -> g_z
// Inner loops: 3x LDS.128 + 8x FFMA2, zero packs, conflict-free smem.
// smem: Ws 64KB + W2s 32KB + AH(dup) 64KB = 160KB
// ---------------------------------------------------------------------------
__global__ void __launch_bounds__(512) k_mlp1(
    const float* __restrict__ x, const float* __restrict__ b1, int n) {
    extern __shared__ float sm[];
    float* Ws  = sm;                   // [k][o] 128x128
    float* W2s = sm + 16384;           // [k][o] 128x64
    float* AH  = sm + 16384 + 8192;    // dup [k][2m] 128x128
    __shared__ float invs[64];
    __shared__ float b1s[HIDC];

    int tid = threadIdx.x;
    int base = blockIdx.x * 64;

    {
        const float4* s4 = (const float4*)g_Wcat;
        float4* d4 = (float4*)Ws;
        for (int i = tid; i < HIDC * HIDC / 4; i += 512) d4[i] = s4[i];
        const float4* s2 = (const float4*)g_W2lT;
        float4* d2 = (float4*)W2s;
        for (int i = tid; i < HIDC * OUTC / 4; i += 512) d2[i] = s2[i];
    }
    if (tid < HIDC) b1s[tid] = b1[tid];
    if (tid < 64) {
        int node = base + tid;
        invs[tid] = (node < n) ? 1.0f / fmaxf(g_deg[node], 1.0f) : 0.f;
    }
    __syncthreads();

    // stage A duplicated: thread (m = tid&63, kg = tid>>6) covers 16 k's
    {
        int m = tid & 63;
        int kg = tid >> 6;
        int node = base + m;
        float inv = invs[m];
        #pragma unroll
        for (int j = 0; j < 4; j++) {
            int k = kg * 16 + j * 4;
            float4 v = make_float4(0.f, 0.f, 0.f, 0.f);
            if (node < n) {
                if (k < 64) {
                    v = *(const float4*)(g_agg1 + (long)node * INC + k);
                    v.x *= inv; v.y *= inv; v.z *= inv; v.w *= inv;
                } else {
                    v = *(const float4*)(x + (long)node * INC + (k - 64));
                }
            }
            ((ull*)(AH + (k + 0) * 128))[m] = pack2(v.x);
            ((ull*)(AH + (k + 1) * 128))[m] = pack2(v.y);
            ((ull*)(AH + (k + 2) * 128))[m] = pack2(v.z);
            ((ull*)(AH + (k + 3) * 128))[m] = pack2(v.w);
        }
    }
    __syncthreads();

    int tx = tid & 31;   // m-pair {2tx, 2tx+1}
    int ty = tid >> 5;   // 0..15 -> GEMM1 o = ty*8..+7; zGEMM o = ty*4..+3

    // ---- GEMM1: 64x128 ----
    ull acc[2][4];
    #pragma unroll
    for (int i = 0; i < 2; i++)
        #pragma unroll
        for (int j = 0; j < 4; j++) acc[i][j] = 0ull;

    #pragma unroll 8
    for (int k = 0; k < HIDC; k++) {
        ulonglong2 aa  = *(ulonglong2*)&AH[k * 128 + 4 * tx];     // dup a_m0, a_m1
        ulonglong2 w01 = *(ulonglong2*)&Ws[k * HIDC + ty * 8];    // broadcast
        ulonglong2 w23 = *(ulonglong2*)&Ws[k * HIDC + ty * 8 + 4];
        fma2(acc[0][0], aa.x, w01.x); fma2(acc[0][1], aa.x, w01.y);
        fma2(acc[0][2], aa.x, w23.x); fma2(acc[0][3], aa.x, w23.y);
        fma2(acc[1][0], aa.y, w01.x); fma2(acc[1][1], aa.y, w01.y);
        fma2(acc[1][2], aa.y, w23.x); fma2(acc[1][3], aa.y, w23.y);
    }
    __syncthreads();   // done reading A before overwriting with H

    // epilogue: bias + relu -> g_h and dup'd H into AH ([o][2m] layout)
    float hv[2][8];
    #pragma unroll
    for (int mi = 0; mi < 2; mi++) {
        int node = base + 2 * tx + mi;
        #pragma unroll
        for (int j = 0; j < 4; j++) {
            float2 p = unpack2(acc[mi][j]);
            int o = ty * 8 + j * 2;
            hv[mi][j * 2]     = fmaxf(p.x + b1s[o], 0.f);
            hv[mi][j * 2 + 1] = fmaxf(p.y + b1s[o + 1], 0.f);
        }
        if (node < n) {
            *(float4*)(g_h + (long)node * HIDC + ty * 8) =
                make_float4(hv[mi][0], hv[mi][1], hv[mi][2], hv[mi][3]);
            *(float4*)(g_h + (long)node * HIDC + ty * 8 + 4) =
                make_float4(hv[mi][4], hv[mi][5], hv[mi][6], hv[mi][7]);
        }
    }
    #pragma unroll
    for (int j = 0; j < 8; j++) {
        ulonglong2 t;
        t.x = pack2(hv[0][j]);
        t.y = pack2(hv[1][j]);
        *(ulonglong2*)&AH[(ty * 8 + j) * 128 + 4 * tx] = t;
    }
    __syncthreads();

    // ---- z GEMM: 64x64 ----
    ull zac[2][2];
    zac[0][0] = zac[0][1] = zac[1][0] = zac[1][1] = 0ull;

    #pragma unroll 8
    for (int k = 0; k < HIDC; k++) {
        ulonglong2 aa = *(ulonglong2*)&AH[k * 128 + 4 * tx];
        ulonglong2 w  = *(ulonglong2*)&W2s[k * OUTC + ty * 4];    // broadcast
        fma2(zac[0][0], aa.x, w.x); fma2(zac[0][1], aa.x, w.y);
        fma2(zac[1][0], aa.y, w.x); fma2(zac[1][1], aa.y, w.y);
    }

    #pragma unroll
    for (int mi = 0; mi < 2; mi++) {
        int node = base + 2 * tx + mi;
        if (node < n) {
            float2 p0 = unpack2(zac[mi][0]);
            float2 p1 = unpack2(zac[mi][1]);
            *(float4*)(g_z + (long)node * OUTC + ty * 4) =
                make_float4(p0.x, p0.y, p1.x, p1.y);
        }
    }
}

// ---------------------------------------------------------------------------
// k_out (512 threads, 64-node tile, 96KB smem -> 2 CTAs/SM):
//   out = sigmoid( inv*zagg + b2 + h @ W2r^T )
// ---------------------------------------------------------------------------
__global__ void __launch_bounds__(512) k_out(
    const float* __restrict__ b2, float* __restrict__ out, int n) {
    extern __shared__ float sm[];
    float* Wr = sm;            // [k][o] 128x64
    float* AD = sm + 8192;     // dup [k][2m] 128x128
    __shared__ float invs[64];
    __shared__ float b2s[OUTC];

    int tid = threadIdx.x;
    int base = blockIdx.x * 64;

    {
        const float4* s4 = (const float4*)g_W2rT;
        float4* d4 = (float4*)Wr;
        for (int i = tid; i < HIDC * OUTC / 4; i += 512) d4[i] = s4[i];
    }
    if (tid < 64) {
        int node = base + tid;
        invs[tid] = (node < n) ? 1.0f / fmaxf(g_deg[node], 1.0f) : 0.f;
        b2s[tid] = b2[tid];
    }

    // stage h duplicated
    {
        int m = tid & 63;
        int kg = tid >> 6;
        int node = base + m;
        #pragma unroll
        for (int j = 0; j < 4; j++) {
            int k = kg * 16 + j * 4;
            float4 v = make_float4(0.f, 0.f, 0.f, 0.f);
            if (node < n) v = *(const float4*)(g_h + (long)node * HIDC + k);
            ((ull*)(AD + (k + 0) * 128))[m] = pack2(v.x);
            ((ull*)(AD + (k + 1) * 128))[m] = pack2(v.y);
            ((ull*)(AD + (k + 2) * 128))[m] = pack2(v.z);
            ((ull*)(AD + (k + 3) * 128))[m] = pack2(v.w);
        }
    }
    __syncthreads();

    int tx = tid & 31;   // m-pair {2tx, 2tx+1}
    int ty = tid >> 5;   // o = ty*4..+3

    ull acc[2][2];
    acc[0][0] = acc[0][1] = acc[1][0] = acc[1][1] = 0ull;

    #pragma unroll 8
    for (int k = 0; k < HIDC; k++) {
        ulonglong2 aa = *(ulonglong2*)&AD[k * 128 + 4 * tx];
        ulonglong2 w  = *(ulonglong2*)&Wr[k * OUTC + ty * 4];
        fma2(acc[0][0], aa.x, w.x); fma2(acc[0][1], aa.x, w.y);
        fma2(acc[1][0], aa.y, w.x); fma2(acc[1][1], aa.y, w.y);
    }

    #pragma unroll
    for (int mi = 0; mi < 2; mi++) {
        int m = 2 * tx + mi;
        int node = base + m;
        if (node < n) {
            float inv = invs[m];
            float4 zg = *(const float4*)(g_zagg + (long)node * OUTC + ty * 4);
            float2 p0 = unpack2(acc[mi][0]);
            float2 p1 = unpack2(acc[mi][1]);
            int o = ty * 4;
            float v0 = p0.x + b2s[o + 0] + inv * zg.x;
            float v1 = p0.y + b2s[o + 1] + inv * zg.y;
            float v2 = p1.x + b2s[o + 2] + inv * zg.z;
            float v3 = p1.y + b2s[o + 3] + inv * zg.w;
            float4 r;
            r.x = 1.0f / (1.0f + __expf(-v0));
            r.y = 1.0f / (1.0f + __expf(-v1));
            r.z = 1.0f / (1.0f + __expf(-v2));
            r.w = 1.0f / (1.0f + __expf(-v3));
            *(float4*)(out + (long)node * OUTC + o) = r;
        }
    }
}

// ---------------------------------------------------------------------------
// kernel_launch  (inputs: x, edge_index, W1_l, W1_r, b1, W2_l, W2_r, b2)
// ---------------------------------------------------------------------------
extern "C" void kernel_launch(void* const* d_in, const int* in_sizes, int n_in,
                              void* d_out, int out_size) {
    const float* x   = (const float*)d_in[0];
    const int*   ei  = (const int*)d_in[1];
    const float* W1l = (const float*)d_in[2];
    const float* W1r = (const float*)d_in[3];
    const float* b1  = (const float*)d_in[4];
    const float* W2l = (const float*)d_in[5];
    const float* W2r = (const float*)d_in[6];
    const float* b2  = (const float*)d_in[7];
    float* out = (float*)d_out;

    int n = in_sizes[0] / INC;
    int E = in_sizes[1] / 2;
    const int* src = ei;
    const int* dst = ei + E;

    const int MLP1_SMEM = (16384 + 8192 + 16384) * 4;  // 160 KB
    const int OUT_SMEM  = (8192 + 16384) * 4;          // 96 KB
    cudaFuncSetAttribute(k_mlp1, cudaFuncAttributeMaxDynamicSharedMemorySize, MLP1_SMEM);
    cudaFuncSetAttribute(k_out, cudaFuncAttributeMaxDynamicSharedMemorySize, OUT_SMEM);

    int nt = (n + 63) / 64;

    k_prep<<<32, 256>>>(W1l, W1r, W2l, W2r);

    {
        long total = (long)n * 32 + (n + 3) / 4;
        int blocks = (int)((total + 255) / 256);
        k_zero<<<blocks, 256>>>(n);
    }
    {
        long total = (long)E * 8;
        int blocks = (int)((total + 255) / 256);
        k_scatter1<<<blocks, 256>>>((const float4*)x, src, dst, E);
    }
    k_mlp1<<<nt, 512, MLP1_SMEM>>>(x, b1, n);
    {
        long total = (long)E * 8;
        int blocks = (int)((total + 255) / 256);
        k_scatter2<<<blocks, 256>>>(src, dst, E);
    }
    k_out<<<nt, 512, OUT_SMEM>>>(b2, out, n);
}

// round 6
// speedup vs baseline: 1.1803x; 1.1803x over previous
#include <cuda_runtime.h>
#include <math.h>

#define NMAX 100000
#define INC 64
#define HIDC 128
#define OUTC 64
#define TM 128   // nodes per GEMM tile

typedef unsigned long long ull;

// Scratch (device globals — no allocation allowed)
__device__ __align__(256) float g_agg1[NMAX * INC];    // 25.6 MB
__device__ __align__(256) float g_h[NMAX * HIDC];      // 51.2 MB
__device__ __align__(256) float g_z[NMAX * OUTC];      // 25.6 MB  z = h @ W2l^T
__device__ __align__(256) float g_zagg[NMAX * OUTC];   // 25.6 MB  scattered z
__device__ __align__(256) float g_deg[NMAX];
// Transposed weights (filled by k_prep each call)
__device__ __align__(256) float g_Wcat[HIDC * HIDC];   // [k][o]: k<64->W1l, k>=64->W1r
__device__ __align__(256) float g_W2lT[HIDC * OUTC];   // [k][o]
__device__ __align__(256) float g_W2rT[HIDC * OUTC];   // [k][o]

// ---------------- packed f32x2 helpers ----------------
__device__ __forceinline__ void fma2(ull& d, ull a, ull b) {
    asm("fma.rn.f32x2 %0, %1, %2, %0;" : "+l"(d) : "l"(a), "l"(b));
}
__device__ __forceinline__ ull pack2(float x) {
    ull r; asm("mov.b64 %0, {%1, %1};" : "=l"(r) : "f"(x)); return r;
}
__device__ __forceinline__ float2 unpack2(ull v) {
    float2 r; asm("mov.b64 {%0, %1}, %2;" : "=f"(r.x), "=f"(r.y) : "l"(v)); return r;
}

// ---------------------------------------------------------------------------
__global__ void k_prep(const float* __restrict__ W1l, const float* __restrict__ W1r,
                       const float* __restrict__ W2l, const float* __restrict__ W2r) {
    int stride = gridDim.x * blockDim.x;
    int tid = blockIdx.x * blockDim.x + threadIdx.x;
    for (int i = tid; i < HIDC * HIDC; i += stride) {
        int k = i >> 7, o = i & 127;
        g_Wcat[i] = (k < 64) ? W1l[o * 64 + k] : W1r[o * 64 + (k - 64)];
    }
    for (int i = tid; i < HIDC * OUTC; i += stride) {
        int k = i >> 6, o = i & 63;
        g_W2lT[i] = W2l[o * 128 + k];
        g_W2rT[i] = W2r[o * 128 + k];
    }
}

// ---------------------------------------------------------------------------
__global__ void k_zero(int n) {
    long t1 = (long)n * (INC / 4);
    long t2 = t1 + (long)n * (OUTC / 4);
    long total = t2 + (n + 3) / 4;
    float4 z = make_float4(0.f, 0.f, 0.f, 0.f);
    for (long i = (long)blockIdx.x * blockDim.x + threadIdx.x; i < total;
         i += (long)gridDim.x * blockDim.x) {
        if (i < t1)       ((float4*)g_agg1)[i] = z;
        else if (i < t2)  ((float4*)g_zagg)[i - t1] = z;
        else              ((float4*)g_deg)[i - t2] = z;
    }
}

__device__ __forceinline__ void red_add_v4(float* addr, float4 v) {
    asm volatile("red.global.add.v4.f32 [%0], {%1,%2,%3,%4};"
                 :: "l"(addr), "f"(v.x), "f"(v.y), "f"(v.z), "f"(v.w)
                 : "memory");
}

// ---------------------------------------------------------------------------
// k_scatter1 (R3 form): 16 threads/edge, float4 each
// ---------------------------------------------------------------------------
__global__ void __launch_bounds__(256) k_scatter1(
    const float4* __restrict__ x4, const int* __restrict__ src,
    const int* __restrict__ dst, int E) {
    long idx = (long)blockIdx.x * blockDim.x + threadIdx.x;
    long total = (long)E * 16;
    if (idx >= total) return;
    int e = (int)(idx >> 4);
    int p = (int)(idx & 15);
    int s = src[e];
    int d = dst[e];
    float4 v = x4[(long)s * 16 + p];
    red_add_v4(g_agg1 + (long)d * INC + p * 4, v);
    if (p == 0) atomicAdd(g_deg + d, 1.0f);
}

// ---------------------------------------------------------------------------
// k_scatter2 (R3 form): 16 threads/edge, float4 each
// ---------------------------------------------------------------------------
__global__ void __launch_bounds__(256) k_scatter2(
    const int* __restrict__ src, const int* __restrict__ dst, int E) {
    long idx = (long)blockIdx.x * blockDim.x + threadIdx.x;
    long total = (long)E * 16;
    if (idx >= total) return;
    int e = (int)(idx >> 4);
    int p = (int)(idx & 15);
    int s = src[e];
    int d = dst[e];
    const float4* z4 = (const float4*)g_z;
    float4 v = z4[(long)s * 16 + p];
    red_add_v4(g_zagg + (long)d * OUTC + p * 4, v);
}

// ---------------------------------------------------------------------------
// k_mlp1 (256 threads, 128-node tile, per-thread 8m x 8o):
//   a = [inv*agg1 , x]  (K=128), A[k][m] in smem
//   h = relu(a @ Wcat + b1)  -> g_h and AH (as [o][m])
//   z = h @ W2l^T            -> g_z
// Inner loop: f32x2 m-pairs native from LDS (no packs on A), W broadcast.
// smem: Ws 64KB + W2s 32KB + AH 64KB = 160KB
// ---------------------------------------------------------------------------
__global__ void __launch_bounds__(256) k_mlp1(
    const float* __restrict__ x, const float* __restrict__ b1, int n) {
    extern __shared__ float sm[];
    float* Ws  = sm;                    // [k][o] 128x128
    float* W2s = sm + 16384;            // [k][o] 128x64
    float* AH  = sm + 16384 + 8192;     // [k][m] 128x128
    __shared__ float invs[TM];
    __shared__ float b1s[HIDC];

    int tid = threadIdx.x;
    int base = blockIdx.x * TM;

    for (int i = tid; i < HIDC * HIDC / 4; i += 256)
        ((float4*)Ws)[i] = ((const float4*)g_Wcat)[i];
    for (int i = tid; i < HIDC * OUTC / 4; i += 256)
        ((float4*)W2s)[i] = ((const float4*)g_W2lT)[i];
    if (tid < HIDC) b1s[tid] = b1[tid];
    if (tid < TM) {
        int node = base + tid;
        invs[tid] = (node < n) ? 1.0f / fmaxf(g_deg[node], 1.0f) : 0.f;
    }
    __syncthreads();

    // stage A[k][m]: thread (m = tid&127, kg = tid>>7) covers 64 k's of node m
    {
        int m = tid & 127;
        int kg = tid >> 7;          // 0 -> agg1 (k 0..63), 1 -> x (k 64..127)
        int node = base + m;
        float inv = invs[m];
        #pragma unroll
        for (int j = 0; j < 16; j++) {
            float4 v = make_float4(0.f, 0.f, 0.f, 0.f);
            if (node < n) {
                if (kg == 0) {
                    v = *(const float4*)(g_agg1 + (long)node * INC + j * 4);
                    v.x *= inv; v.y *= inv; v.z *= inv; v.w *= inv;
                } else {
                    v = *(const float4*)(x + (long)node * INC + j * 4);
                }
            }
            int k = kg * 64 + j * 4;
            AH[(k + 0) * TM + m] = v.x;
            AH[(k + 1) * TM + m] = v.y;
            AH[(k + 2) * TM + m] = v.z;
            AH[(k + 3) * TM + m] = v.w;
        }
    }
    __syncthreads();

    int tx = tid & 15;          // m-block: mb..mb+7
    int ty = tid >> 4;          // o-block: ob..ob+7 (GEMM1) / o2..o2+3 (zGEMM)
    int mb = tx * 8;
    int ob = ty * 8;

    // ---- GEMM1: 128x128, acc[mpair][o] ----
    ull acc[4][8];
    #pragma unroll
    for (int i = 0; i < 4; i++)
        #pragma unroll
        for (int j = 0; j < 8; j++) acc[i][j] = 0ull;

    #pragma unroll 4
    for (int k = 0; k < HIDC; k++) {
        ulonglong2 a01 = *(ulonglong2*)&AH[k * TM + mb];       // m-pairs {0,1},{2,3}
        ulonglong2 a23 = *(ulonglong2*)&AH[k * TM + mb + 4];   // {4,5},{6,7}
        float4 w0 = *(float4*)&Ws[k * HIDC + ob];
        float4 w1 = *(float4*)&Ws[k * HIDC + ob + 4];
        ull wd[8];
        wd[0] = pack2(w0.x); wd[1] = pack2(w0.y); wd[2] = pack2(w0.z); wd[3] = pack2(w0.w);
        wd[4] = pack2(w1.x); wd[5] = pack2(w1.y); wd[6] = pack2(w1.z); wd[7] = pack2(w1.w);
        ull av0 = a01.x, av1 = a01.y, av2 = a23.x, av3 = a23.y;
        #pragma unroll
        for (int j = 0; j < 8; j++) {
            fma2(acc[0][j], av0, wd[j]);
            fma2(acc[1][j], av1, wd[j]);
            fma2(acc[2][j], av2, wd[j]);
            fma2(acc[3][j], av3, wd[j]);
        }
    }

    // bias + relu
    float2 hv[4][8];
    #pragma unroll
    for (int mp = 0; mp < 4; mp++)
        #pragma unroll
        for (int j = 0; j < 8; j++) {
            float2 p = unpack2(acc[mp][j]);
            float bb = b1s[ob + j];
            hv[mp][j].x = fmaxf(p.x + bb, 0.f);
            hv[mp][j].y = fmaxf(p.y + bb, 0.f);
        }

    // g_h stores (before overwriting AH is fine; gmem only)
    #pragma unroll
    for (int mp = 0; mp < 4; mp++) {
        #pragma unroll
        for (int e = 0; e < 2; e++) {
            int node = base + mb + 2 * mp + e;
            if (node < n) {
                float4 lo, hi;
                if (e == 0) {
                    lo = make_float4(hv[mp][0].x, hv[mp][1].x, hv[mp][2].x, hv[mp][3].x);
                    hi = make_float4(hv[mp][4].x, hv[mp][5].x, hv[mp][6].x, hv[mp][7].x);
                } else {
                    lo = make_float4(hv[mp][0].y, hv[mp][1].y, hv[mp][2].y, hv[mp][3].y);
                    hi = make_float4(hv[mp][4].y, hv[mp][5].y, hv[mp][6].y, hv[mp][7].y);
                }
                *(float4*)(g_h + (long)node * HIDC + ob)     = lo;
                *(float4*)(g_h + (long)node * HIDC + ob + 4) = hi;
            }
        }
    }
    __syncthreads();   // everyone done reading A

    // write H into AH as [o][m]
    #pragma unroll
    for (int j = 0; j < 8; j++) {
        float4 q0 = make_float4(hv[0][j].x, hv[0][j].y, hv[1][j].x, hv[1][j].y);
        float4 q1 = make_float4(hv[2][j].x, hv[2][j].y, hv[3][j].x, hv[3][j].y);
        *(float4*)&AH[(ob + j) * TM + mb]     = q0;
        *(float4*)&AH[(ob + j) * TM + mb + 4] = q1;
    }
    __syncthreads();

    // ---- zGEMM: 128x64, per-thread 8m x 4o ----
    int o2 = ty * 4;
    ull zac[4][4];
    #pragma unroll
    for (int i = 0; i < 4; i++)
        #pragma unroll
        for (int j = 0; j < 4; j++) zac[i][j] = 0ull;

    #pragma unroll 4
    for (int k = 0; k < HIDC; k++) {
        ulonglong2 a01 = *(ulonglong2*)&AH[k * TM + mb];
        ulonglong2 a23 = *(ulonglong2*)&AH[k * TM + mb + 4];
        float4 w = *(float4*)&W2s[k * OUTC + o2];
        ull wd[4];
        wd[0] = pack2(w.x); wd[1] = pack2(w.y); wd[2] = pack2(w.z); wd[3] = pack2(w.w);
        ull av0 = a01.x, av1 = a01.y, av2 = a23.x, av3 = a23.y;
        #pragma unroll
        for (int j = 0; j < 4; j++) {
            fma2(zac[0][j], av0, wd[j]);
            fma2(zac[1][j], av1, wd[j]);
            fma2(zac[2][j], av2, wd[j]);
            fma2(zac[3][j], av3, wd[j]);
        }
    }

    #pragma unroll
    for (int mp = 0; mp < 4; mp++) {
        float2 p0 = unpack2(zac[mp][0]);
        float2 p1 = unpack2(zac[mp][1]);
        float2 p2 = unpack2(zac[mp][2]);
        float2 p3 = unpack2(zac[mp][3]);
        int n0 = base + mb + 2 * mp;
        if (n0 < n)
            *(float4*)(g_z + (long)n0 * OUTC + o2) = make_float4(p0.x, p1.x, p2.x, p3.x);
        if (n0 + 1 < n)
            *(float4*)(g_z + (long)(n0 + 1) * OUTC + o2) = make_float4(p0.y, p1.y, p2.y, p3.y);
    }
}

// ---------------------------------------------------------------------------
// k_out (256 threads, 128-node tile, per-thread 8m x 4o, 96KB smem):
//   out = sigmoid( inv*zagg + b2 + h @ W2r^T )
// ---------------------------------------------------------------------------
__global__ void __launch_bounds__(256) k_out(
    const float* __restrict__ b2, float* __restrict__ out, int n) {
    extern __shared__ float sm[];
    float* Wr = sm;            // [k][o] 128x64
    float* AD = sm + 8192;     // [k][m] 128x128
    __shared__ float invs[TM];
    __shared__ float b2s[OUTC];

    int tid = threadIdx.x;
    int base = blockIdx.x * TM;

    for (int i = tid; i < HIDC * OUTC / 4; i += 256)
        ((float4*)Wr)[i] = ((const float4*)g_W2rT)[i];
    if (tid < OUTC) b2s[tid] = b2[tid];
    if (tid < TM) {
        int node = base + tid;
        invs[tid] = (node < n) ? 1.0f / fmaxf(g_deg[node], 1.0f) : 0.f;
    }

    // stage h: thread (m = tid&127, kg = tid>>7) covers 64 k's
    {
        int m = tid & 127;
        int kg = tid >> 7;
        int node = base + m;
        #pragma unroll
        for (int j = 0; j < 16; j++) {
            int k = kg * 64 + j * 4;
            float4 v = make_float4(0.f, 0.f, 0.f, 0.f);
            if (node < n) v = *(const float4*)(g_h + (long)node * HIDC + k);
            AD[(k + 0) * TM + m] = v.x;
            AD[(k + 1) * TM + m] = v.y;
            AD[(k + 2) * TM + m] = v.z;
            AD[(k + 3) * TM + m] = v.w;
        }
    }
    __syncthreads();

    int tx = tid & 15;
    int ty = tid >> 4;
    int mb = tx * 8;
    int o2 = ty * 4;

    ull acc[4][4];
    #pragma unroll
    for (int i = 0; i < 4; i++)
        #pragma unroll
        for (int j = 0; j < 4; j++) acc[i][j] = 0ull;

    #pragma unroll 4
    for (int k = 0; k < HIDC; k++) {
        ulonglong2 a01 = *(ulonglong2*)&AD[k * TM + mb];
        ulonglong2 a23 = *(ulonglong2*)&AD[k * TM + mb + 4];
        float4 w = *(float4*)&Wr[k * OUTC + o2];
        ull wd[4];
        wd[0] = pack2(w.x); wd[1] = pack2(w.y); wd[2] = pack2(w.z); wd[3] = pack2(w.w);
        ull av0 = a01.x, av1 = a01.y, av2 = a23.x, av3 = a23.y;
        #pragma unroll
        for (int j = 0; j < 4; j++) {
            fma2(acc[0][j], av0, wd[j]);
            fma2(acc[1][j], av1, wd[j]);
            fma2(acc[2][j], av2, wd[j]);
            fma2(acc[3][j], av3, wd[j]);
        }
    }

    #pragma unroll
    for (int mp = 0; mp < 4; mp++) {
        float2 p0 = unpack2(acc[mp][0]);
        float2 p1 = unpack2(acc[mp][1]);
        float2 p2 = unpack2(acc[mp][2]);
        float2 p3 = unpack2(acc[mp][3]);
        #pragma unroll
        for (int e = 0; e < 2; e++) {
            int m = mb + 2 * mp + e;
            int node = base + m;
            if (node < n) {
                float inv = invs[m];
                float4 zg = *(const float4*)(g_zagg + (long)node * OUTC + o2);
                float s0 = (e == 0 ? p0.x : p0.y) + b2s[o2 + 0] + inv * zg.x;
                float s1 = (e == 0 ? p1.x : p1.y) + b2s[o2 + 1] + inv * zg.y;
                float s2 = (e == 0 ? p2.x : p2.y) + b2s[o2 + 2] + inv * zg.z;
                float s3 = (e == 0 ? p3.x : p3.y) + b2s[o2 + 3] + inv * zg.w;
                float4 r;
                r.x = 1.0f / (1.0f + __expf(-s0));
                r.y = 1.0f / (1.0f + __expf(-s1));
                r.z = 1.0f / (1.0f + __expf(-s2));
                r.w = 1.0f / (1.0f + __expf(-s3));
                *(float4*)(out + (long)node * OUTC + o2) = r;
            }
        }
    }
}

// ---------------------------------------------------------------------------
// kernel_launch  (inputs: x, edge_index, W1_l, W1_r, b1, W2_l, W2_r, b2)
// ---------------------------------------------------------------------------
extern "C" void kernel_launch(void* const* d_in, const int* in_sizes, int n_in,
                              void* d_out, int out_size) {
    const float* x   = (const float*)d_in[0];
    const int*   ei  = (const int*)d_in[1];
    const float* W1l = (const float*)d_in[2];
    const float* W1r = (const float*)d_in[3];
    const float* b1  = (const float*)d_in[4];
    const float* W2l = (const float*)d_in[5];
    const float* W2r = (const float*)d_in[6];
    const float* b2  = (const float*)d_in[7];
    float* out = (float*)d_out;

    int n = in_sizes[0] / INC;
    int E = in_sizes[1] / 2;
    const int* src = ei;
    const int* dst = ei + E;

    const int MLP1_SMEM = (16384 + 8192 + 16384) * 4;  // 160 KB
    const int OUT_SMEM  = (8192 + 16384) * 4;          // 96 KB
    cudaFuncSetAttribute(k_mlp1, cudaFuncAttributeMaxDynamicSharedMemorySize, MLP1_SMEM);
    cudaFuncSetAttribute(k_out, cudaFuncAttributeMaxDynamicSharedMemorySize, OUT_SMEM);

    int nt = (n + TM - 1) / TM;

    k_prep<<<32, 256>>>(W1l, W1r, W2l, W2r);

    {
        long total = (long)n * 32 + (n + 3) / 4;
        int blocks = (int)((total + 255) / 256);
        k_zero<<<blocks, 256>>>(n);
    }
    {
        long total = (long)E * 16;
        int blocks = (int)((total + 255) / 256);
        k_scatter1<<<blocks, 256>>>((const float4*)x, src, dst, E);
    }
    k_mlp1<<<nt, 256, MLP1_SMEM>>>(x, b1, n);
    {
        long total = (long)E * 16;
        int blocks = (int)((total + 255) / 256);
        k_scatter2<<<blocks, 256>>>(src, dst, E);
    }
    k_out<<<nt, 256, OUT_SMEM>>>(b2, out, n);
}

// round 9
// speedup vs baseline: 1.3791x; 1.1684x over previous
#include <cuda_runtime.h>
#include <math.h>

#define NMAX 100000
#define INC 64
#define HIDC 128
#define OUTC 64
#define TM 80      // nodes per GEMM tile
#define AST 84     // A row stride (floats): 84%4==0 (16B align), 84*4%32==16.. bank-safe

typedef unsigned long long ull;

// Scratch (device globals — no allocation allowed)
__device__ __align__(256) float g_agg1[NMAX * INC];    // 25.6 MB
__device__ __align__(256) float g_h[NMAX * HIDC];      // 51.2 MB
__device__ __align__(256) float g_z[NMAX * OUTC];      // 25.6 MB  z = h @ W2l^T
__device__ __align__(256) float g_r[NMAX * OUTC];      // 25.6 MB  r = h @ W2r^T
__device__ __align__(256) float g_zagg[NMAX * OUTC];   // 25.6 MB  scattered z
__device__ __align__(256) float g_deg[NMAX];
// Transposed weights (filled by k_prep each call)
__device__ __align__(256) float g_Wcat[HIDC * HIDC];   // [k][o]: k<64->W1l, k>=64->W1r
__device__ __align__(256) float g_Wzr[HIDC * HIDC];    // [k][o]: o<64->W2l, o>=64->W2r

// ---------------- packed f32x2 helpers ----------------
__device__ __forceinline__ void fma2(ull& d, ull a, ull b) {
    asm("fma.rn.f32x2 %0, %1, %2, %0;" : "+l"(d) : "l"(a), "l"(b));
}
__device__ __forceinline__ ull pack2(float x) {
    ull r; asm("mov.b64 %0, {%1, %1};" : "=l"(r) : "f"(x)); return r;
}
__device__ __forceinline__ float2 unpack2(ull v) {
    float2 r; asm("mov.b64 {%0, %1}, %2;" : "=f"(r.x), "=f"(r.y) : "l"(v)); return r;
}

// ---------------------------------------------------------------------------
__global__ void k_prep(const float* __restrict__ W1l, const float* __restrict__ W1r,
                       const float* __restrict__ W2l, const float* __restrict__ W2r) {
    int stride = gridDim.x * blockDim.x;
    int tid = blockIdx.x * blockDim.x + threadIdx.x;
    for (int i = tid; i < HIDC * HIDC; i += stride) {
        int k = i >> 7, o = i & 127;
        g_Wcat[i] = (k < 64) ? W1l[o * 64 + k] : W1r[o * 64 + (k - 64)];
        g_Wzr[i]  = (o < 64) ? W2l[o * 128 + k] : W2r[(o - 64) * 128 + k];
    }
}

// ---------------------------------------------------------------------------
__global__ void k_zero(int n) {
    long t1 = (long)n * (INC / 4);
    long t2 = t1 + (long)n * (OUTC / 4);
    long total = t2 + (n + 3) / 4;
    float4 z = make_float4(0.f, 0.f, 0.f, 0.f);
    for (long i = (long)blockIdx.x * blockDim.x + threadIdx.x; i < total;
         i += (long)gridDim.x * blockDim.x) {
        if (i < t1)       ((float4*)g_agg1)[i] = z;
        else if (i < t2)  ((float4*)g_zagg)[i - t1] = z;
        else              ((float4*)g_deg)[i - t2] = z;
    }
}

__device__ __forceinline__ void red_add_v4(float* addr, float4 v) {
    asm volatile("red.global.add.v4.f32 [%0], {%1,%2,%3,%4};"
                 :: "l"(addr), "f"(v.x), "f"(v.y), "f"(v.z), "f"(v.w)
                 : "memory");
}

// ---------------------------------------------------------------------------
// k_scatter1: agg1[dst] += x[src]  (16 threads/edge, float4) + deg
// ---------------------------------------------------------------------------
__global__ void __launch_bounds__(256) k_scatter1(
    const float4* __restrict__ x4, const int* __restrict__ src,
    const int* __restrict__ dst, int E) {
    long idx = (long)blockIdx.x * blockDim.x + threadIdx.x;
    long total = (long)E * 16;
    if (idx >= total) return;
    int e = (int)(idx >> 4);
    int p = (int)(idx & 15);
    int s = src[e];
    int d = dst[e];
    float4 v = x4[(long)s * 16 + p];
    red_add_v4(g_agg1 + (long)d * INC + p * 4, v);
    if (p == 0) atomicAdd(g_deg + d, 1.0f);
}

// ---------------------------------------------------------------------------
// k_scatter2: zagg[dst] += z[src]  (16 threads/edge, float4)
// ---------------------------------------------------------------------------
__global__ void __launch_bounds__(256) k_scatter2(
    const int* __restrict__ src, const int* __restrict__ dst, int E) {
    long idx = (long)blockIdx.x * blockDim.x + threadIdx.x;
    long total = (long)E * 16;
    if (idx >= total) return;
    int e = (int)(idx >> 4);
    int p = (int)(idx & 15);
    int s = src[e];
    int d = dst[e];
    const float4* z4 = (const float4*)g_z;
    float4 v = z4[(long)s * 16 + p];
    red_add_v4(g_zagg + (long)d * OUTC + p * 4, v);
}

// ---------------------------------------------------------------------------
// k_mlp1 (160 threads, 80-node tile, 8m x 8o per thread, 2 CTAs/SM):
//   a = [inv*agg1 , x] (K=128);  h = relu(a @ Wcat + b1) -> g_h
// smem: Ws 64KB + A[k][AST] 42KB + b1s = ~107KB
// ---------------------------------------------------------------------------
__global__ void __launch_bounds__(160, 2) k_mlp1(
    const float* __restrict__ x, const float* __restrict__ b1, int n) {
    extern __shared__ float sm[];
    float* Ws  = sm;                    // [k][o] 128x128
    float* A   = sm + 16384;            // [k][m] 128 x AST
    float* b1s = sm + 16384 + HIDC * AST;

    int tid = threadIdx.x;
    int base = blockIdx.x * TM;

    for (int i = tid; i < HIDC * HIDC / 4; i += 160)
        ((float4*)Ws)[i] = ((const float4*)g_Wcat)[i];
    if (tid < HIDC) b1s[tid] = b1[tid];

    // stage A[k][m]: warp w, pass p -> node base+p*5+w; lane owns k = lane+32i
    {
        int lane = tid & 31;
        int w = tid >> 5;               // 0..4
        #pragma unroll
        for (int p = 0; p < 16; p++) {
            int m = p * 5 + w;
            int node = base + m;
            float v0 = 0.f, v1 = 0.f, v2 = 0.f, v3 = 0.f;
            if (node < n) {
                float inv = 1.0f / fmaxf(g_deg[node], 1.0f);
                v0 = g_agg1[(long)node * INC + lane] * inv;
                v1 = g_agg1[(long)node * INC + 32 + lane] * inv;
                v2 = x[(long)node * INC + lane];
                v3 = x[(long)node * INC + 32 + lane];
            }
            A[(lane)      * AST + m] = v0;
            A[(lane + 32) * AST + m] = v1;
            A[(lane + 64) * AST + m] = v2;
            A[(lane + 96) * AST + m] = v3;
        }
    }
    __syncthreads();

    int ob = (tid & 15) * 8;
    int mb = (tid >> 4) * 8;            // 0..9 -> mb 0..72

    ull acc[4][8];
    #pragma unroll
    for (int i = 0; i < 4; i++)
        #pragma unroll
        for (int j = 0; j < 8; j++) acc[i][j] = 0ull;

    #pragma unroll 8
    for (int k = 0; k < HIDC; k++) {
        ulonglong2 a01 = *(ulonglong2*)&A[k * AST + mb];       // m pairs {0,1},{2,3}
        ulonglong2 a23 = *(ulonglong2*)&A[k * AST + mb + 4];   // {4,5},{6,7}
        float4 w0 = *(float4*)&Ws[k * HIDC + ob];
        float4 w1 = *(float4*)&Ws[k * HIDC + ob + 4];
        ull wd[8];
        wd[0] = pack2(w0.x); wd[1] = pack2(w0.y); wd[2] = pack2(w0.z); wd[3] = pack2(w0.w);
        wd[4] = pack2(w1.x); wd[5] = pack2(w1.y); wd[6] = pack2(w1.z); wd[7] = pack2(w1.w);
        ull av0 = a01.x, av1 = a01.y, av2 = a23.x, av3 = a23.y;
        #pragma unroll
        for (int j = 0; j < 8; j++) {
            fma2(acc[0][j], av0, wd[j]);
            fma2(acc[1][j], av1, wd[j]);
            fma2(acc[2][j], av2, wd[j]);
            fma2(acc[3][j], av3, wd[j]);
        }
    }

    // epilogue: bias + relu -> g_h
    #pragma unroll
    for (int mp = 0; mp < 4; mp++) {
        float2 hv[8];
        #pragma unroll
        for (int j = 0; j < 8; j++) {
            float2 p = unpack2(acc[mp][j]);
            float bb = b1s[ob + j];
            hv[j].x = fmaxf(p.x + bb, 0.f);
            hv[j].y = fmaxf(p.y + bb, 0.f);
        }
        #pragma unroll
        for (int e = 0; e < 2; e++) {
            int node = base + mb + 2 * mp + e;
            if (node < n) {
                float4 lo, hi;
                if (e == 0) {
                    lo = make_float4(hv[0].x, hv[1].x, hv[2].x, hv[3].x);
                    hi = make_float4(hv[4].x, hv[5].x, hv[6].x, hv[7].x);
                } else {
                    lo = make_float4(hv[0].y, hv[1].y, hv[2].y, hv[3].y);
                    hi = make_float4(hv[4].y, hv[5].y, hv[6].y, hv[7].y);
                }
                *(float4*)(g_h + (long)node * HIDC + ob)     = lo;
                *(float4*)(g_h + (long)node * HIDC + ob + 4) = hi;
            }
        }
    }
}

// ---------------------------------------------------------------------------
// k_mlp2 (160 threads, 80-node tile, 2 CTAs/SM):
//   [z|r] = h @ [W2l^T | W2r^T]   (o<64 -> g_z, o>=64 -> g_r)
// smem: Wzr 64KB + A 42KB = ~106KB
// ---------------------------------------------------------------------------
__global__ void __launch_bounds__(160, 2) k_mlp2(int n) {
    extern __shared__ float sm[];
    float* Ws = sm;                     // [k][o] 128x128  (Wzr)
    float* A  = sm + 16384;             // [k][m] 128 x AST  (h)

    int tid = threadIdx.x;
    int base = blockIdx.x * TM;

    for (int i = tid; i < HIDC * HIDC / 4; i += 160)
        ((float4*)Ws)[i] = ((const float4*)g_Wzr)[i];

    // stage h[k][m]
    {
        int lane = tid & 31;
        int w = tid >> 5;
        #pragma unroll
        for (int p = 0; p < 16; p++) {
            int m = p * 5 + w;
            int node = base + m;
            float v0 = 0.f, v1 = 0.f, v2 = 0.f, v3 = 0.f;
            if (node < n) {
                const float* hrow = g_h + (long)node * HIDC;
                v0 = hrow[lane];
                v1 = hrow[32 + lane];
                v2 = hrow[64 + lane];
                v3 = hrow[96 + lane];
            }
            A[(lane)      * AST + m] = v0;
            A[(lane + 32) * AST + m] = v1;
            A[(lane + 64) * AST + m] = v2;
            A[(lane + 96) * AST + m] = v3;
        }
    }
    __syncthreads();

    int ob = (tid & 15) * 8;
    int mb = (tid >> 4) * 8;

    ull acc[4][8];
    #pragma unroll
    for (int i = 0; i < 4; i++)
        #pragma unroll
        for (int j = 0; j < 8; j++) acc[i][j] = 0ull;

    #pragma unroll 8
    for (int k = 0; k < HIDC; k++) {
        ulonglong2 a01 = *(ulonglong2*)&A[k * AST + mb];
        ulonglong2 a23 = *(ulonglong2*)&A[k * AST + mb + 4];
        float4 w0 = *(float4*)&Ws[k * HIDC + ob];
        float4 w1 = *(float4*)&Ws[k * HIDC + ob + 4];
        ull wd[8];
        wd[0] = pack2(w0.x); wd[1] = pack2(w0.y); wd[2] = pack2(w0.z); wd[3] = pack2(w0.w);
        wd[4] = pack2(w1.x); wd[5] = pack2(w1.y); wd[6] = pack2(w1.z); wd[7] = pack2(w1.w);
        ull av0 = a01.x, av1 = a01.y, av2 = a23.x, av3 = a23.y;
        #pragma unroll
        for (int j = 0; j < 8; j++) {
            fma2(acc[0][j], av0, wd[j]);
            fma2(acc[1][j], av1, wd[j]);
            fma2(acc[2][j], av2, wd[j]);
            fma2(acc[3][j], av3, wd[j]);
        }
    }

    // epilogue: route to g_z (o<64) or g_r (o>=64); no bias/act here
    float* dst = (ob < 64) ? g_z : g_r;
    int oc = (ob < 64) ? ob : (ob - 64);
    #pragma unroll
    for (int mp = 0; mp < 4; mp++) {
        float2 p0 = unpack2(acc[mp][0]);
        float2 p1 = unpack2(acc[mp][1]);
        float2 p2 = unpack2(acc[mp][2]);
        float2 p3 = unpack2(acc[mp][3]);
        float2 p4 = unpack2(acc[mp][4]);
        float2 p5 = unpack2(acc[mp][5]);
        float2 p6 = unpack2(acc[mp][6]);
        float2 p7 = unpack2(acc[mp][7]);
        int n0 = base + mb + 2 * mp;
        if (n0 < n) {
            *(float4*)(dst + (long)n0 * OUTC + oc)     = make_float4(p0.x, p1.x, p2.x, p3.x);
            *(float4*)(dst + (long)n0 * OUTC + oc + 4) = make_float4(p4.x, p5.x, p6.x, p7.x);
        }
        if (n0 + 1 < n) {
            *(float4*)(dst + (long)(n0 + 1) * OUTC + oc)     = make_float4(p0.y, p1.y, p2.y, p3.y);
            *(float4*)(dst + (long)(n0 + 1) * OUTC + oc + 4) = make_float4(p4.y, p5.y, p6.y, p7.y);
        }
    }
}

// ---------------------------------------------------------------------------
// k_out_elem: out = sigmoid( r + b2 + inv*zagg )   pure elementwise
// ---------------------------------------------------------------------------
__global__ void __launch_bounds__(256) k_out_elem(
    const float* __restrict__ b2, float* __restrict__ out, int n) {
    long i = (long)blockIdx.x * blockDim.x + threadIdx.x;
    long total = (long)n * (OUTC / 4);
    if (i >= total) return;
    int node = (int)(i >> 4);
    int q = (int)(i & 15);
    float inv = 1.0f / fmaxf(g_deg[node], 1.0f);
    float4 r  = ((const float4*)g_r)[i];
    float4 zg = ((const float4*)g_zagg)[i];
    float4 bb = *(const float4*)(b2 + q * 4);
    float s0 = r.x + bb.x + inv * zg.x;
    float s1 = r.y + bb.y + inv * zg.y;
    float s2 = r.z + bb.z + inv * zg.z;
    float s3 = r.w + bb.w + inv * zg.w;
    float4 o;
    o.x = 1.0f / (1.0f + __expf(-s0));
    o.y = 1.0f / (1.0f + __expf(-s1));
    o.z = 1.0f / (1.0f + __expf(-s2));
    o.w = 1.0f / (1.0f + __expf(-s3));
    ((float4*)out)[i] = o;
}

// ---------------------------------------------------------------------------
// kernel_launch  (inputs: x, edge_index, W1_l, W1_r, b1, W2_l, W2_r, b2)
// ---------------------------------------------------------------------------
extern "C" void kernel_launch(void* const* d_in, const int* in_sizes, int n_in,
                              void* d_out, int out_size) {
    const float* x   = (const float*)d_in[0];
    const int*   ei  = (const int*)d_in[1];
    const float* W1l = (const float*)d_in[2];
    const float* W1r = (const float*)d_in[3];
    const float* b1  = (const float*)d_in[4];
    const float* W2l = (const float*)d_in[5];
    const float* W2r = (const float*)d_in[6];
    const float* b2  = (const float*)d_in[7];
    float* out = (float*)d_out;

    int n = in_sizes[0] / INC;
    int E = in_sizes[1] / 2;
    const int* src = ei;
    const int* dst = ei + E;

    const int MLP1_SMEM = (16384 + HIDC * AST + HIDC) * 4;  // ~107 KB
    const int MLP2_SMEM = (16384 + HIDC * AST) * 4;         // ~106 KB
    cudaFuncSetAttribute(k_mlp1, cudaFuncAttributeMaxDynamicSharedMemorySize, MLP1_SMEM);
    cudaFuncSetAttribute(k_mlp2, cudaFuncAttributeMaxDynamicSharedMemorySize, MLP2_SMEM);

    int nt = (n + TM - 1) / TM;

    k_prep<<<64, 256>>>(W1l, W1r, W2l, W2r);

    {
        long total = (long)n * 32 + (n + 3) / 4;
        int blocks = (int)((total + 255) / 256);
        k_zero<<<blocks, 256>>>(n);
    }
    {
        long total = (long)E * 16;
        int blocks = (int)((total + 255) / 256);
        k_scatter1<<<blocks, 256>>>((const float4*)x, src, dst, E);
    }
    k_mlp1<<<nt, 160, MLP1_SMEM>>>(x, b1, n);
    k_mlp2<<<nt, 160, MLP2_SMEM>>>(n);
    {
        long total = (long)E * 16;
        int blocks = (int)((total + 255) / 256);
        k_scatter2<<<blocks, 256>>>(src, dst, E);
    }
    {
        long total = (long)n * 16;
        int blocks = (int)((total + 255) / 256);
        k_out_elem<<<blocks, 256>>>(b2, out, n);
    }
}

// round 12
// speedup vs baseline: 1.7094x; 1.2395x over previous
#include <cuda_runtime.h>
#include <cuda_bf16.h>
#include <math.h>
#include <cstdint>

#define NMAX 100000
#define INC 64
#define HIDC 128
#define OUTC 64
#define TMT 128      // nodes per tensor tile
#define SBF 136      // padded bf16 row stride (68 words == 4 mod 32 -> conflict-free frags)
#define ROWB 272     // SBF * 2 bytes

typedef uint32_t u32;

// ---------------------------------------------------------------------------
// Scratch (device globals — no allocation allowed)
// ---------------------------------------------------------------------------
__device__ __align__(256) float g_agg1[NMAX * INC];
__device__ __align__(256) float g_h[NMAX * HIDC];
__device__ __align__(256) float g_z[NMAX * OUTC];     // z = h @ W2l^T
__device__ __align__(256) float g_r[NMAX * OUTC];     // r = h @ W2r^T
__device__ __align__(256) float g_zagg[NMAX * OUTC];
__device__ __align__(256) float g_deg[NMAX];
// bf16 hi/lo split weights, padded [o][k] row-major (stride SBF)
__device__ __align__(256) __nv_bfloat16 g_Wc_hi[HIDC * SBF];
__device__ __align__(256) __nv_bfloat16 g_Wc_lo[HIDC * SBF];
__device__ __align__(256) __nv_bfloat16 g_Wz_hi[HIDC * SBF];
__device__ __align__(256) __nv_bfloat16 g_Wz_lo[HIDC * SBF];

// ---------------------------------------------------------------------------
__device__ __forceinline__ u32 bf16pair(float a, float b) {
    __nv_bfloat162 t = __floats2bfloat162_rn(a, b);
    return *reinterpret_cast<u32*>(&t);
}
// split float4 (4 consecutive k) into hi/lo bf16 pairs; returns via out params
__device__ __forceinline__ void split4(float4 v, u32& h0, u32& h1, u32& l0, u32& l1) {
    __nv_bfloat16 hx = __float2bfloat16(v.x), hy = __float2bfloat16(v.y);
    __nv_bfloat16 hz = __float2bfloat16(v.z), hw = __float2bfloat16(v.w);
    h0 = bf16pair(__bfloat162float(hx), __bfloat162float(hy));
    h1 = bf16pair(__bfloat162float(hz), __bfloat162float(hw));
    l0 = bf16pair(v.x - __bfloat162float(hx), v.y - __bfloat162float(hy));
    l1 = bf16pair(v.z - __bfloat162float(hz), v.w - __bfloat162float(hw));
}

// m16n8k16 row.col bf16 MMA (baseline PTX — assembles for plain sm_103)
__device__ __forceinline__ void mma16816(float* c, const u32* a, const u32* b) {
    asm volatile(
        "mma.sync.aligned.m16n8k16.row.col.f32.bf16.bf16.f32 "
        "{%0,%1,%2,%3}, {%4,%5,%6,%7}, {%8,%9}, {%0,%1,%2,%3};"
        : "+f"(c[0]), "+f"(c[1]), "+f"(c[2]), "+f"(c[3])
        : "r"(a[0]), "r"(a[1]), "r"(a[2]), "r"(a[3]), "r"(b[0]), "r"(b[1]));
}

// smem layout (bytes)
#define SM_AH 0
#define SM_AL (HIDC * ROWB)             // 34816
#define SM_WH (2 * HIDC * ROWB)
#define SM_WL (3 * HIDC * ROWB)
#define SM_BIAS (4 * HIDC * ROWB)
#define SM_TOT (4 * HIDC * ROWB + 512)  // ~139.8 KB

// ---------------------------------------------------------------------------
// k_prep: hi/lo split weights into padded [o][k] layout
//   Wcat row o: k<64 -> W1l[o][k], else W1r[o][k-64]
//   Wzr  row o: o<64 -> W2l[o][k], else W2r[o-64][k]
// ---------------------------------------------------------------------------
__global__ void k_prep(const float* __restrict__ W1l, const float* __restrict__ W1r,
                       const float* __restrict__ W2l, const float* __restrict__ W2r) {
    int stride = gridDim.x * blockDim.x;
    for (int i = blockIdx.x * blockDim.x + threadIdx.x; i < HIDC * HIDC; i += stride) {
        int o = i >> 7, k = i & 127;
        float wc = (k < 64) ? W1l[o * 64 + k] : W1r[o * 64 + (k - 64)];
        float wz = (o < 64) ? W2l[o * 128 + k] : W2r[(o - 64) * 128 + k];
        int off = o * SBF + k;
        __nv_bfloat16 ch = __float2bfloat16(wc);
        __nv_bfloat16 zh = __float2bfloat16(wz);
        g_Wc_hi[off] = ch;
        g_Wc_lo[off] = __float2bfloat16(wc - __bfloat162float(ch));
        g_Wz_hi[off] = zh;
        g_Wz_lo[off] = __float2bfloat16(wz - __bfloat162float(zh));
    }
}

// ---------------------------------------------------------------------------
__global__ void k_zero(int n) {
    long t1 = (long)n * (INC / 4);
    long t2 = t1 + (long)n * (OUTC / 4);
    long total = t2 + (n + 3) / 4;
    float4 z = make_float4(0.f, 0.f, 0.f, 0.f);
    for (long i = (long)blockIdx.x * blockDim.x + threadIdx.x; i < total;
         i += (long)gridDim.x * blockDim.x) {
        if (i < t1)       ((float4*)g_agg1)[i] = z;
        else if (i < t2)  ((float4*)g_zagg)[i - t1] = z;
        else              ((float4*)g_deg)[i - t2] = z;
    }
}

__device__ __forceinline__ void red_add_v4(float* addr, float4 v) {
    asm volatile("red.global.add.v4.f32 [%0], {%1,%2,%3,%4};"
                 :: "l"(addr), "f"(v.x), "f"(v.y), "f"(v.z), "f"(v.w) : "memory");
}

// ---------------------------------------------------------------------------
__global__ void __launch_bounds__(256) k_scatter1(
    const float4* __restrict__ x4, const int* __restrict__ src,
    const int* __restrict__ dst, int E) {
    long idx = (long)blockIdx.x * blockDim.x + threadIdx.x;
    long total = (long)E * 16;
    if (idx >= total) return;
    int e = (int)(idx >> 4);
    int p = (int)(idx & 15);
    int s = src[e];
    int d = dst[e];
    float4 v = x4[(long)s * 16 + p];
    red_add_v4(g_agg1 + (long)d * INC + p * 4, v);
    if (p == 0) atomicAdd(g_deg + d, 1.0f);
}

__global__ void __launch_bounds__(256) k_scatter2(
    const int* __restrict__ src, const int* __restrict__ dst, int E) {
    long idx = (long)blockIdx.x * blockDim.x + threadIdx.x;
    long total = (long)E * 16;
    if (idx >= total) return;
    int e = (int)(idx >> 4);
    int p = (int)(idx & 15);
    int s = src[e];
    int d = dst[e];
    const float4* z4 = (const float4*)g_z;
    float4 v = z4[(long)s * 16 + p];
    red_add_v4(g_zagg + (long)d * OUTC + p * 4, v);
}

// ---------------------------------------------------------------------------
// GEMM mainloop shared by both MLP kernels.
// Warp w: m-rows [ (w>>1)*32 , +32 ), n-cols [ (w&1)*64 , +64 ).
// acc[mi][ni][4] accumulated over 8 k-steps x 3 split passes.
// ---------------------------------------------------------------------------
__device__ __forceinline__ void gemm_mainloop(const char* smc, int warp, int lane,
                                              float acc[2][8][4]) {
    int g = lane >> 2;
    int t = lane & 3;
    int mt2 = warp >> 1;
    int ng = warp & 1;

    const char* arow0 = smc + SM_AH + (mt2 * 32 + g) * ROWB;
    const char* wrow0 = smc + SM_WH + (ng * 64 + g) * ROWB;
    const ptrdiff_t LO = SM_AL - SM_AH;   // same delta for W (SM_WL - SM_WH)

    #pragma unroll
    for (int ks = 0; ks < 8; ks++) {
        int kb = (ks * 16 + 2 * t) * 2;   // byte offset of first frag element
        u32 ah[2][4], al[2][4], wh[8][2], wl[8][2];
        #pragma unroll
        for (int mi = 0; mi < 2; mi++) {
            const char* rp = arow0 + mi * 16 * ROWB;
            ah[mi][0] = *(const u32*)(rp + kb);
            ah[mi][1] = *(const u32*)(rp + 8 * ROWB + kb);
            ah[mi][2] = *(const u32*)(rp + kb + 16);
            ah[mi][3] = *(const u32*)(rp + 8 * ROWB + kb + 16);
            al[mi][0] = *(const u32*)(rp + LO + kb);
            al[mi][1] = *(const u32*)(rp + LO + 8 * ROWB + kb);
            al[mi][2] = *(const u32*)(rp + LO + kb + 16);
            al[mi][3] = *(const u32*)(rp + LO + 8 * ROWB + kb + 16);
        }
        #pragma unroll
        for (int ni = 0; ni < 8; ni++) {
            const char* wp = wrow0 + ni * 8 * ROWB;
            wh[ni][0] = *(const u32*)(wp + kb);
            wh[ni][1] = *(const u32*)(wp + kb + 16);
            wl[ni][0] = *(const u32*)(wp + LO + kb);
            wl[ni][1] = *(const u32*)(wp + LO + kb + 16);
        }
        #pragma unroll
        for (int ni = 0; ni < 8; ni++) {
            #pragma unroll
            for (int mi = 0; mi < 2; mi++) {
                mma16816(acc[mi][ni], ah[mi], wh[ni]);   // hi*hi
                mma16816(acc[mi][ni], ah[mi], wl[ni]);   // hi*lo
                mma16816(acc[mi][ni], al[mi], wh[ni]);   // lo*hi
            }
        }
    }
}

// ---------------------------------------------------------------------------
// k_mlp1_mma (256 thr, 128-node tile): h = relu([inv*agg1, x] @ Wcat^T + b1)
// ---------------------------------------------------------------------------
__global__ void __launch_bounds__(256) k_mlp1_mma(
    const float* __restrict__ x, const float* __restrict__ b1, int n) {
    extern __shared__ char smc[];
    int tid = threadIdx.x;
    int warp = tid >> 5;
    int lane = tid & 31;
    int base = blockIdx.x * TMT;

    // stage weights (flat copies; pad bytes carried over, never read as frags >=128)
    for (int i = tid; i < HIDC * ROWB / 16; i += 256) {
        ((float4*)(smc + SM_WH))[i] = ((const float4*)g_Wc_hi)[i];
        ((float4*)(smc + SM_WL))[i] = ((const float4*)g_Wc_lo)[i];
    }
    if (tid < HIDC) ((float*)(smc + SM_BIAS))[tid] = b1[tid];

    // stage A: row m = tid>>1; half = tid&1 covers 64 cols
    {
        int m = tid >> 1;
        int half = tid & 1;
        int node = base + m;
        char* rowh = smc + SM_AH + m * ROWB + half * 128;
        char* rowl = smc + SM_AL + m * ROWB + half * 128;
        float inv = 0.f;
        if (half == 0 && node < n) inv = 1.0f / fmaxf(g_deg[node], 1.0f);
        #pragma unroll
        for (int q = 0; q < 16; q++) {
            float4 v = make_float4(0.f, 0.f, 0.f, 0.f);
            if (node < n) {
                if (half == 0) {   // cols 0..63 = inv * agg1
                    v = *(const float4*)(g_agg1 + (long)node * INC + q * 4);
                    v.x *= inv; v.y *= inv; v.z *= inv; v.w *= inv;
                } else {           // cols 64..127 = x
                    v = *(const float4*)(x + (long)node * INC + q * 4);
                }
            }
            u32 h0, h1, l0, l1;
            split4(v, h0, h1, l0, l1);
            *(uint2*)(rowh + q * 8) = make_uint2(h0, h1);
            *(uint2*)(rowl + q * 8) = make_uint2(l0, l1);
        }
    }
    __syncthreads();

    float acc[2][8][4];
    #pragma unroll
    for (int a = 0; a < 2; a++)
        #pragma unroll
        for (int b = 0; b < 8; b++)
            #pragma unroll
            for (int c = 0; c < 4; c++) acc[a][b][c] = 0.f;

    gemm_mainloop(smc, warp, lane, acc);

    // epilogue: bias + relu -> g_h
    {
        int g = lane >> 2;
        int t = lane & 3;
        int mt2 = warp >> 1;
        int ng = warp & 1;
        const float* bias = (const float*)(smc + SM_BIAS);
        #pragma unroll
        for (int ni = 0; ni < 8; ni++) {
            int c = ng * 64 + ni * 8 + 2 * t;
            float b0v = bias[c], b1v = bias[c + 1];
            #pragma unroll
            for (int mi = 0; mi < 2; mi++) {
                int r0 = base + mt2 * 32 + mi * 16 + g;
                if (r0 < n) {
                    float2 o = make_float2(fmaxf(acc[mi][ni][0] + b0v, 0.f),
                                           fmaxf(acc[mi][ni][1] + b1v, 0.f));
                    *(float2*)(g_h + (long)r0 * HIDC + c) = o;
                }
                int r1 = r0 + 8;
                if (r1 < n) {
                    float2 o = make_float2(fmaxf(acc[mi][ni][2] + b0v, 0.f),
                                           fmaxf(acc[mi][ni][3] + b1v, 0.f));
                    *(float2*)(g_h + (long)r1 * HIDC + c) = o;
                }
            }
        }
    }
}

// ---------------------------------------------------------------------------
// k_mlp2_mma (256 thr, 128-node tile): [z|r] = h @ Wzr^T  (cols<64 -> z, else r)
// ---------------------------------------------------------------------------
__global__ void __launch_bounds__(256) k_mlp2_mma(int n) {
    extern __shared__ char smc[];
    int tid = threadIdx.x;
    int warp = tid >> 5;
    int lane = tid & 31;
    int base = blockIdx.x * TMT;

    for (int i = tid; i < HIDC * ROWB / 16; i += 256) {
        ((float4*)(smc + SM_WH))[i] = ((const float4*)g_Wz_hi)[i];
        ((float4*)(smc + SM_WL))[i] = ((const float4*)g_Wz_lo)[i];
    }

    // stage A = h
    {
        int m = tid >> 1;
        int half = tid & 1;
        int node = base + m;
        char* rowh = smc + SM_AH + m * ROWB + half * 128;
        char* rowl = smc + SM_AL + m * ROWB + half * 128;
        #pragma unroll
        for (int q = 0; q < 16; q++) {
            float4 v = make_float4(0.f, 0.f, 0.f, 0.f);
            if (node < n)
                v = *(const float4*)(g_h + (long)node * HIDC + half * 64 + q * 4);
            u32 h0, h1, l0, l1;
            split4(v, h0, h1, l0, l1);
            *(uint2*)(rowh + q * 8) = make_uint2(h0, h1);
            *(uint2*)(rowl + q * 8) = make_uint2(l0, l1);
        }
    }
    __syncthreads();

    float acc[2][8][4];
    #pragma unroll
    for (int a = 0; a < 2; a++)
        #pragma unroll
        for (int b = 0; b < 8; b++)
            #pragma unroll
            for (int c = 0; c < 4; c++) acc[a][b][c] = 0.f;

    gemm_mainloop(smc, warp, lane, acc);

    // epilogue: ng==0 -> g_z cols 0..63, ng==1 -> g_r cols 0..63
    {
        int g = lane >> 2;
        int t = lane & 3;
        int mt2 = warp >> 1;
        int ng = warp & 1;
        float* dstp = (ng == 0) ? g_z : g_r;
        #pragma unroll
        for (int ni = 0; ni < 8; ni++) {
            int oc = ni * 8 + 2 * t;
            #pragma unroll
            for (int mi = 0; mi < 2; mi++) {
                int r0 = base + mt2 * 32 + mi * 16 + g;
                if (r0 < n)
                    *(float2*)(dstp + (long)r0 * OUTC + oc) =
                        make_float2(acc[mi][ni][0], acc[mi][ni][1]);
                int r1 = r0 + 8;
                if (r1 < n)
                    *(float2*)(dstp + (long)r1 * OUTC + oc) =
                        make_float2(acc[mi][ni][2], acc[mi][ni][3]);
            }
        }
    }
}

// ---------------------------------------------------------------------------
// k_out_elem: out = sigmoid( r + b2 + inv*zagg )
// ---------------------------------------------------------------------------
__global__ void __launch_bounds__(256) k_out_elem(
    const float* __restrict__ b2, float* __restrict__ out, int n) {
    long i = (long)blockIdx.x * blockDim.x + threadIdx.x;
    long total = (long)n * (OUTC / 4);
    if (i >= total) return;
    int node = (int)(i >> 4);
    int q = (int)(i & 15);
    float inv = 1.0f / fmaxf(g_deg[node], 1.0f);
    float4 r  = ((const float4*)g_r)[i];
    float4 zg = ((const float4*)g_zagg)[i];
    float4 bb = *(const float4*)(b2 + q * 4);
    float s0 = r.x + bb.x + inv * zg.x;
    float s1 = r.y + bb.y + inv * zg.y;
    float s2 = r.z + bb.z + inv * zg.z;
    float s3 = r.w + bb.w + inv * zg.w;
    float4 o;
    o.x = 1.0f / (1.0f + __expf(-s0));
    o.y = 1.0f / (1.0f + __expf(-s1));
    o.z = 1.0f / (1.0f + __expf(-s2));
    o.w = 1.0f / (1.0f + __expf(-s3));
    ((float4*)out)[i] = o;
}

// ---------------------------------------------------------------------------
// kernel_launch  (inputs: x, edge_index, W1_l, W1_r, b1, W2_l, W2_r, b2)
// ---------------------------------------------------------------------------
extern "C" void kernel_launch(void* const* d_in, const int* in_sizes, int n_in,
                              void* d_out, int out_size) {
    const float* x   = (const float*)d_in[0];
    const int*   ei  = (const int*)d_in[1];
    const float* W1l = (const float*)d_in[2];
    const float* W1r = (const float*)d_in[3];
    const float* b1  = (const float*)d_in[4];
    const float* W2l = (const float*)d_in[5];
    const float* W2r = (const float*)d_in[6];
    const float* b2  = (const float*)d_in[7];
    float* out = (float*)d_out;

    int n = in_sizes[0] / INC;
    int E = in_sizes[1] / 2;
    const int* src = ei;
    const int* dst = ei + E;

    cudaFuncSetAttribute(k_mlp1_mma, cudaFuncAttributeMaxDynamicSharedMemorySize, SM_TOT);
    cudaFuncSetAttribute(k_mlp2_mma, cudaFuncAttributeMaxDynamicSharedMemorySize, SM_TOT);

    int nt = (n + TMT - 1) / TMT;

    k_prep<<<64, 256>>>(W1l, W1r, W2l, W2r);

    {
        long total = (long)n * 32 + (n + 3) / 4;
        int blocks = (int)((total + 255) / 256);
        k_zero<<<blocks, 256>>>(n);
    }
    {
        long total = (long)E * 16;
        int blocks = (int)((total + 255) / 256);
        k_scatter1<<<blocks, 256>>>((const float4*)x, src, dst, E);
    }
    k_mlp1_mma<<<nt, 256, SM_TOT>>>(x, b1, n);
    k_mlp2_mma<<<nt, 256, SM_TOT>>>(n);
    {
        long total = (long)E * 16;
        int blocks = (int)((total + 255) / 256);
        k_scatter2<<<blocks, 256>>>(src, dst, E);
    }
    {
        long total = (long)n * 16;
        int blocks = (int)((total + 255) / 256);
        k_out_elem<<<blocks, 256>>>(b2, out, n);
    }
}

// round 14
// speedup vs baseline: 2.7302x; 1.5972x over previous
#include <cuda_runtime.h>
#include <cuda_bf16.h>
#include <math.h>
#include <cstdint>

#define NMAX 100000
#define EMAX 1600000
#define INC 64
#define HIDC 128
#define OUTC 64
#define TMT 128      // nodes per tensor tile
#define SBF 136      // padded bf16 row stride (68 words == 4 mod 32 -> conflict-free frags)
#define ROWB 272     // SBF * 2 bytes

typedef uint32_t u32;

// ---------------------------------------------------------------------------
// Scratch (device globals — no allocation allowed)
// ---------------------------------------------------------------------------
__device__ __align__(256) float g_agg1m[NMAX * INC];   // mean-aggregated x
__device__ __align__(256) float g_z[NMAX * OUTC];      // z = h @ W2l^T
__device__ __align__(256) float g_r[NMAX * OUTC];      // r = h @ W2r^T
__device__ __align__(256) float g_zaggm[NMAX * OUTC];  // mean-aggregated z
__device__ __align__(256) int   g_cnt[NMAX];
__device__ __align__(256) int   g_off[NMAX];
__device__ __align__(256) int   g_cur[NMAX];
__device__ __align__(256) int   g_bsum[256];
__device__ __align__(256) int   g_ssrc[EMAX];
// bf16 hi/lo split weights, padded [o][k] row-major (stride SBF)
__device__ __align__(256) __nv_bfloat16 g_Wc_hi[HIDC * SBF];
__device__ __align__(256) __nv_bfloat16 g_Wc_lo[HIDC * SBF];
__device__ __align__(256) __nv_bfloat16 g_Wz_hi[HIDC * SBF];
__device__ __align__(256) __nv_bfloat16 g_Wz_lo[HIDC * SBF];

// ---------------------------------------------------------------------------
__device__ __forceinline__ u32 bf16pair(float a, float b) {
    __nv_bfloat162 t = __floats2bfloat162_rn(a, b);
    return *reinterpret_cast<u32*>(&t);
}
__device__ __forceinline__ void split4(float4 v, u32& h0, u32& h1, u32& l0, u32& l1) {
    __nv_bfloat16 hx = __float2bfloat16(v.x), hy = __float2bfloat16(v.y);
    __nv_bfloat16 hz = __float2bfloat16(v.z), hw = __float2bfloat16(v.w);
    h0 = bf16pair(__bfloat162float(hx), __bfloat162float(hy));
    h1 = bf16pair(__bfloat162float(hz), __bfloat162float(hw));
    l0 = bf16pair(v.x - __bfloat162float(hx), v.y - __bfloat162float(hy));
    l1 = bf16pair(v.z - __bfloat162float(hz), v.w - __bfloat162float(hw));
}
__device__ __forceinline__ void mma16816(float* c, const u32* a, const u32* b) {
    asm volatile(
        "mma.sync.aligned.m16n8k16.row.col.f32.bf16.bf16.f32 "
        "{%0,%1,%2,%3}, {%4,%5,%6,%7}, {%8,%9}, {%0,%1,%2,%3};"
        : "+f"(c[0]), "+f"(c[1]), "+f"(c[2]), "+f"(c[3])
        : "r"(a[0]), "r"(a[1]), "r"(a[2]), "r"(a[3]), "r"(b[0]), "r"(b[1]));
}

// smem layout (bytes) for the fused MLP kernel
#define SM_AH 0
#define SM_AL (HIDC * ROWB)
#define SM_W1H (2 * HIDC * ROWB)
#define SM_W1L (3 * HIDC * ROWB)
#define SM_W2H (4 * HIDC * ROWB)
#define SM_W2L (5 * HIDC * ROWB)
#define SM_BIAS (6 * HIDC * ROWB)
#define SM_TOT (6 * HIDC * ROWB + 512)   // ~204.9 KB

// ---------------------------------------------------------------------------
// k_prep: hi/lo split weights into padded [o][k] layout
// ---------------------------------------------------------------------------
__global__ void k_prep(const float* __restrict__ W1l, const float* __restrict__ W1r,
                       const float* __restrict__ W2l, const float* __restrict__ W2r) {
    int stride = gridDim.x * blockDim.x;
    for (int i = blockIdx.x * blockDim.x + threadIdx.x; i < HIDC * HIDC; i += stride) {
        int o = i >> 7, k = i & 127;
        float wc = (k < 64) ? W1l[o * 64 + k] : W1r[o * 64 + (k - 64)];
        float wz = (o < 64) ? W2l[o * 128 + k] : W2r[(o - 64) * 128 + k];
        int off = o * SBF + k;
        __nv_bfloat16 ch = __float2bfloat16(wc);
        __nv_bfloat16 zh = __float2bfloat16(wz);
        g_Wc_hi[off] = ch;
        g_Wc_lo[off] = __float2bfloat16(wc - __bfloat162float(ch));
        g_Wz_hi[off] = zh;
        g_Wz_lo[off] = __float2bfloat16(wz - __bfloat162float(zh));
    }
}

// ---------------------------------------------------------------------------
// CSR build: hist -> scan -> reorder
// ---------------------------------------------------------------------------
__global__ void k_zero_cnt(int n) {
    int i = blockIdx.x * blockDim.x + threadIdx.x;
    if (i < n) g_cnt[i] = 0;
}
__global__ void k_hist(const int* __restrict__ dst, int E) {
    for (int e = blockIdx.x * blockDim.x + threadIdx.x; e < E; e += gridDim.x * blockDim.x)
        atomicAdd(&g_cnt[dst[e]], 1);
}
// block-level exclusive scan (1024/block) + block totals
__global__ void k_scan1(int n) {
    __shared__ int s[1024];
    int t = threadIdx.x;
    int i = blockIdx.x * 1024 + t;
    int v = (i < n) ? g_cnt[i] : 0;
    s[t] = v;
    __syncthreads();
    #pragma unroll
    for (int o = 1; o < 1024; o <<= 1) {
        int tmp = (t >= o) ? s[t - o] : 0;
        __syncthreads();
        s[t] += tmp;
        __syncthreads();
    }
    if (i < n) g_off[i] = s[t] - v;        // exclusive
    if (t == 1023) g_bsum[blockIdx.x] = s[t];
}
__global__ void k_scan2(int nb) {
    if (threadIdx.x == 0) {
        int run = 0;
        for (int b = 0; b < nb; b++) { int v = g_bsum[b]; g_bsum[b] = run; run += v; }
    }
}
__global__ void k_scan3(int n) {
    for (int i = blockIdx.x * blockDim.x + threadIdx.x; i < n; i += gridDim.x * blockDim.x) {
        int o = g_off[i] + g_bsum[i >> 10];
        g_off[i] = o;
        g_cur[i] = o;
    }
}
__global__ void k_reorder(const int* __restrict__ src, const int* __restrict__ dst, int E) {
    for (int e = blockIdx.x * blockDim.x + threadIdx.x; e < E; e += gridDim.x * blockDim.x) {
        int pos = atomicAdd(&g_cur[dst[e]], 1);
        g_ssrc[pos] = src[e];
    }
}

// ---------------------------------------------------------------------------
// k_gather1: agg1m[d] = mean_{s in N(d)} x[s]   (16 threads per dst, float4 each)
// ---------------------------------------------------------------------------
__global__ void __launch_bounds__(256) k_gather1(const float4* __restrict__ x4, int n) {
    int d = blockIdx.x * 16 + (threadIdx.x >> 4);
    int p = threadIdx.x & 15;
    if (d >= n) return;
    int off = g_off[d];
    int cnt = g_cnt[d];
    int end = off + cnt;
    float4 a0 = make_float4(0.f, 0.f, 0.f, 0.f);
    float4 a1 = make_float4(0.f, 0.f, 0.f, 0.f);
    int j = off;
    for (; j + 1 < end; j += 2) {
        int s0 = g_ssrc[j], s1 = g_ssrc[j + 1];
        float4 v0 = x4[(long)s0 * 16 + p];
        float4 v1 = x4[(long)s1 * 16 + p];
        a0.x += v0.x; a0.y += v0.y; a0.z += v0.z; a0.w += v0.w;
        a1.x += v1.x; a1.y += v1.y; a1.z += v1.z; a1.w += v1.w;
    }
    if (j < end) {
        float4 v = x4[(long)g_ssrc[j] * 16 + p];
        a0.x += v.x; a0.y += v.y; a0.z += v.z; a0.w += v.w;
    }
    float inv = 1.0f / fmaxf((float)cnt, 1.0f);
    float4 o = make_float4((a0.x + a1.x) * inv, (a0.y + a1.y) * inv,
                           (a0.z + a1.z) * inv, (a0.w + a1.w) * inv);
    ((float4*)g_agg1m)[(long)d * 16 + p] = o;
}

// ---------------------------------------------------------------------------
// k_gather2: zaggm[d] = mean_{s in N(d)} z[s]
// ---------------------------------------------------------------------------
__global__ void __launch_bounds__(256) k_gather2(int n) {
    int d = blockIdx.x * 16 + (threadIdx.x >> 4);
    int p = threadIdx.x & 15;
    if (d >= n) return;
    int off = g_off[d];
    int cnt = g_cnt[d];
    int end = off + cnt;
    const float4* z4 = (const float4*)g_z;
    float4 a0 = make_float4(0.f, 0.f, 0.f, 0.f);
    float4 a1 = make_float4(0.f, 0.f, 0.f, 0.f);
    int j = off;
    for (; j + 1 < end; j += 2) {
        int s0 = g_ssrc[j], s1 = g_ssrc[j + 1];
        float4 v0 = z4[(long)s0 * 16 + p];
        float4 v1 = z4[(long)s1 * 16 + p];
        a0.x += v0.x; a0.y += v0.y; a0.z += v0.z; a0.w += v0.w;
        a1.x += v1.x; a1.y += v1.y; a1.z += v1.z; a1.w += v1.w;
    }
    if (j < end) {
        float4 v = z4[(long)g_ssrc[j] * 16 + p];
        a0.x += v.x; a0.y += v.y; a0.z += v.z; a0.w += v.w;
    }
    float inv = 1.0f / fmaxf((float)cnt, 1.0f);
    float4 o = make_float4((a0.x + a1.x) * inv, (a0.y + a1.y) * inv,
                           (a0.z + a1.z) * inv, (a0.w + a1.w) * inv);
    ((float4*)g_zaggm)[(long)d * 16 + p] = o;
}

// ---------------------------------------------------------------------------
// GEMM mainloop (wbase selects W1 or W2 region)
// Warp w: m-rows [(w>>1)*32, +32), n-cols [(w&1)*64, +64)
// ---------------------------------------------------------------------------
__device__ __forceinline__ void gemm_mainloop(const char* smc, int wbase,
                                              int warp, int lane, float acc[2][8][4]) {
    int g = lane >> 2;
    int t = lane & 3;
    int mt2 = warp >> 1;
    int ng = warp & 1;
    const char* arow0 = smc + SM_AH + (mt2 * 32 + g) * ROWB;
    const char* wrow0 = smc + wbase + (ng * 64 + g) * ROWB;
    const ptrdiff_t LO = SM_AL - SM_AH;   // hi->lo delta (same for W regions)

    #pragma unroll
    for (int ks = 0; ks < 8; ks++) {
        int kb = (ks * 16 + 2 * t) * 2;
        u32 ah[2][4], al[2][4], wh[8][2], wl[8][2];
        #pragma unroll
        for (int mi = 0; mi < 2; mi++) {
            const char* rp = arow0 + mi * 16 * ROWB;
            ah[mi][0] = *(const u32*)(rp + kb);
            ah[mi][1] = *(const u32*)(rp + 8 * ROWB + kb);
            ah[mi][2] = *(const u32*)(rp + kb + 16);
            ah[mi][3] = *(const u32*)(rp + 8 * ROWB + kb + 16);
            al[mi][0] = *(const u32*)(rp + LO + kb);
            al[mi][1] = *(const u32*)(rp + LO + 8 * ROWB + kb);
            al[mi][2] = *(const u32*)(rp + LO + kb + 16);
            al[mi][3] = *(const u32*)(rp + LO + 8 * ROWB + kb + 16);
        }
        #pragma unroll
        for (int ni = 0; ni < 8; ni++) {
            const char* wp = wrow0 + ni * 8 * ROWB;
            wh[ni][0] = *(const u32*)(wp + kb);
            wh[ni][1] = *(const u32*)(wp + kb + 16);
            wl[ni][0] = *(const u32*)(wp + LO + kb);
            wl[ni][1] = *(const u32*)(wp + LO + kb + 16);
        }
        #pragma unroll
        for (int ni = 0; ni < 8; ni++) {
            #pragma unroll
            for (int mi = 0; mi < 2; mi++) {
                mma16816(acc[mi][ni], ah[mi], wh[ni]);
                mma16816(acc[mi][ni], ah[mi], wl[ni]);
                mma16816(acc[mi][ni], al[mi], wh[ni]);
            }
        }
    }
}

// ---------------------------------------------------------------------------
// k_mlp_fused (256 thr, 128-node tile):
//   h = relu([agg1m, x] @ W1^T + b1)   (h stays in smem, split hi/lo)
//   [z|r] = h @ Wzr^T -> g_z / g_r
// ---------------------------------------------------------------------------
__global__ void __launch_bounds__(256) k_mlp_fused(
    const float* __restrict__ x, const float* __restrict__ b1, int n) {
    extern __shared__ char smc[];
    int tid = threadIdx.x;
    int warp = tid >> 5;
    int lane = tid & 31;
    int base = blockIdx.x * TMT;

    // stage both weight sets (flat copies)
    for (int i = tid; i < HIDC * ROWB / 16; i += 256) {
        ((float4*)(smc + SM_W1H))[i] = ((const float4*)g_Wc_hi)[i];
        ((float4*)(smc + SM_W1L))[i] = ((const float4*)g_Wc_lo)[i];
        ((float4*)(smc + SM_W2H))[i] = ((const float4*)g_Wz_hi)[i];
        ((float4*)(smc + SM_W2L))[i] = ((const float4*)g_Wz_lo)[i];
    }
    if (tid < HIDC) ((float*)(smc + SM_BIAS))[tid] = b1[tid];

    // stage A1: row m = tid>>1; half 0 = agg1m (already mean), half 1 = x
    {
        int m = tid >> 1;
        int half = tid & 1;
        int node = base + m;
        char* rowh = smc + SM_AH + m * ROWB + half * 128;
        char* rowl = smc + SM_AL + m * ROWB + half * 128;
        #pragma unroll
        for (int q = 0; q < 16; q++) {
            float4 v = make_float4(0.f, 0.f, 0.f, 0.f);
            if (node < n) {
                v = (half == 0)
                    ? *(const float4*)(g_agg1m + (long)node * INC + q * 4)
                    : *(const float4*)(x + (long)node * INC + q * 4);
            }
            u32 h0, h1, l0, l1;
            split4(v, h0, h1, l0, l1);
            *(uint2*)(rowh + q * 8) = make_uint2(h0, h1);
            *(uint2*)(rowl + q * 8) = make_uint2(l0, l1);
        }
    }
    __syncthreads();

    int g = lane >> 2;
    int t = lane & 3;
    int mt2 = warp >> 1;
    int ng = warp & 1;

    float acc[2][8][4];
    #pragma unroll
    for (int a = 0; a < 2; a++)
        #pragma unroll
        for (int b = 0; b < 8; b++)
            #pragma unroll
            for (int c = 0; c < 4; c++) acc[a][b][c] = 0.f;

    // ---- GEMM1 ----
    gemm_mainloop(smc, SM_W1H, warp, lane, acc);
    __syncthreads();   // all warps done reading A1 before overwrite

    // epilogue1: bias + relu, split h hi/lo back into A buffers
    {
        const float* bias = (const float*)(smc + SM_BIAS);
        #pragma unroll
        for (int ni = 0; ni < 8; ni++) {
            int c = ng * 64 + ni * 8 + 2 * t;
            float b0v = bias[c], b1v = bias[c + 1];
            #pragma unroll
            for (int mi = 0; mi < 2; mi++) {
                #pragma unroll
                for (int rr = 0; rr < 2; rr++) {
                    int r = mt2 * 32 + mi * 16 + rr * 8 + g;
                    float v0 = fmaxf(acc[mi][ni][rr * 2 + 0] + b0v, 0.f);
                    float v1 = fmaxf(acc[mi][ni][rr * 2 + 1] + b1v, 0.f);
                    __nv_bfloat16 h0 = __float2bfloat16(v0);
                    __nv_bfloat16 h1 = __float2bfloat16(v1);
                    u32 hp = bf16pair(__bfloat162float(h0), __bfloat162float(h1));
                    u32 lp = bf16pair(v0 - __bfloat162float(h0), v1 - __bfloat162float(h1));
                    *(u32*)(smc + SM_AH + r * ROWB + c * 2) = hp;
                    *(u32*)(smc + SM_AL + r * ROWB + c * 2) = lp;
                }
            }
        }
    }
    __syncthreads();

    #pragma unroll
    for (int a = 0; a < 2; a++)
        #pragma unroll
        for (int b = 0; b < 8; b++)
            #pragma unroll
            for (int c = 0; c < 4; c++) acc[a][b][c] = 0.f;

    // ---- GEMM2 ----
    gemm_mainloop(smc, SM_W2H, warp, lane, acc);

    // epilogue2: ng==0 -> g_z, ng==1 -> g_r (cols 0..63 each)
    {
        float* dstp = (ng == 0) ? g_z : g_r;
        #pragma unroll
        for (int ni = 0; ni < 8; ni++) {
            int oc = ni * 8 + 2 * t;
            #pragma unroll
            for (int mi = 0; mi < 2; mi++) {
                int r0 = base + mt2 * 32 + mi * 16 + g;
                if (r0 < n)
                    *(float2*)(dstp + (long)r0 * OUTC + oc) =
                        make_float2(acc[mi][ni][0], acc[mi][ni][1]);
                int r1 = r0 + 8;
                if (r1 < n)
                    *(float2*)(dstp + (long)r1 * OUTC + oc) =
                        make_float2(acc[mi][ni][2], acc[mi][ni][3]);
            }
        }
    }
}

// ---------------------------------------------------------------------------
// k_out_elem: out = sigmoid( r + b2 + zaggm )   (zaggm already mean)
// ---------------------------------------------------------------------------
__global__ void __launch_bounds__(256) k_out_elem(
    const float* __restrict__ b2, float* __restrict__ out, int n) {
    long i = (long)blockIdx.x * blockDim.x + threadIdx.x;
    long total = (long)n * (OUTC / 4);
    if (i >= total) return;
    int q = (int)(i & 15);
    float4 r  = ((const float4*)g_r)[i];
    float4 zg = ((const float4*)g_zaggm)[i];
    float4 bb = *(const float4*)(b2 + q * 4);
    float s0 = r.x + bb.x + zg.x;
    float s1 = r.y + bb.y + zg.y;
    float s2 = r.z + bb.z + zg.z;
    float s3 = r.w + bb.w + zg.w;
    float4 o;
    o.x = 1.0f / (1.0f + __expf(-s0));
    o.y = 1.0f / (1.0f + __expf(-s1));
    o.z = 1.0f / (1.0f + __expf(-s2));
    o.w = 1.0f / (1.0f + __expf(-s3));
    ((float4*)out)[i] = o;
}

// ---------------------------------------------------------------------------
// kernel_launch  (inputs: x, edge_index, W1_l, W1_r, b1, W2_l, W2_r, b2)
// ---------------------------------------------------------------------------
extern "C" void kernel_launch(void* const* d_in, const int* in_sizes, int n_in,
                              void* d_out, int out_size) {
    const float* x   = (const float*)d_in[0];
    const int*   ei  = (const int*)d_in[1];
    const float* W1l = (const float*)d_in[2];
    const float* W1r = (const float*)d_in[3];
    const float* b1  = (const float*)d_in[4];
    const float* W2l = (const float*)d_in[5];
    const float* W2r = (const float*)d_in[6];
    const float* b2  = (const float*)d_in[7];
    float* out = (float*)d_out;

    int n = in_sizes[0] / INC;
    int E = in_sizes[1] / 2;
    const int* src = ei;
    const int* dst = ei + E;

    cudaFuncSetAttribute(k_mlp_fused, cudaFuncAttributeMaxDynamicSharedMemorySize, SM_TOT);

    int nt = (n + TMT - 1) / TMT;
    int nb = (n + 1023) / 1024;

    k_prep<<<64, 256>>>(W1l, W1r, W2l, W2r);

    // --- CSR build ---
    k_zero_cnt<<<(n + 255) / 256, 256>>>(n);
    k_hist<<<1024, 256>>>(dst, E);
    k_scan1<<<nb, 1024>>>(n);
    k_scan2<<<1, 32>>>(nb);
    k_scan3<<<(n + 255) / 256, 256>>>(n);
    k_reorder<<<1024, 256>>>(src, dst, E);

    // --- layer 1 aggregate + fused dense ---
    k_gather1<<<(n + 15) / 16, 256>>>((const float4*)x, n);
    k_mlp_fused<<<nt, 256, SM_TOT>>>(x, b1, n);

    // --- layer 2 aggregate + output ---
    k_gather2<<<(n + 15) / 16, 256>>>(n);
    {
        long total = (long)n * 16;
        int blocks = (int)((total + 255) / 256);
        k_out_elem<<<blocks, 256>>>(b2, out, n);
    }
}

// round 17
// speedup vs baseline: 2.8851x; 1.0567x over previous
#include <cuda_runtime.h>
#include <cuda_bf16.h>
#include <math.h>
#include <cstdint>

#define NMAX 100000
#define EMAX 1600000
#define INC 64
#define HIDC 128
#define OUTC 64
#define TMT 128      // nodes per tensor tile
#define SBF 136      // padded bf16 row stride (68 words == 4 mod 32 -> conflict-free frags)
#define ROWB 272     // SBF * 2 bytes

typedef uint32_t u32;

// ---------------------------------------------------------------------------
// Scratch (device globals — no allocation allowed)
// ---------------------------------------------------------------------------
__device__ __align__(256) float g_agg1m[NMAX * INC];   // mean-aggregated x
__device__ __align__(256) float g_z[NMAX * OUTC];      // z = h @ W2l^T
__device__ __align__(256) float g_r[NMAX * OUTC];      // r = h @ W2r^T
__device__ __align__(256) int   g_cnt[NMAX];
__device__ __align__(256) int   g_off[NMAX];
__device__ __align__(256) int   g_cur[NMAX];
__device__ __align__(256) int   g_bsum[256];
__device__ __align__(256) int   g_ssrc[EMAX];
// bf16 hi/lo split weights, padded [o][k] row-major (stride SBF)
__device__ __align__(256) __nv_bfloat16 g_Wc_hi[HIDC * SBF];
__device__ __align__(256) __nv_bfloat16 g_Wc_lo[HIDC * SBF];
__device__ __align__(256) __nv_bfloat16 g_Wz_hi[HIDC * SBF];
__device__ __align__(256) __nv_bfloat16 g_Wz_lo[HIDC * SBF];

// ---------------------------------------------------------------------------
__device__ __forceinline__ u32 bf16pair(float a, float b) {
    __nv_bfloat162 t = __floats2bfloat162_rn(a, b);
    return *reinterpret_cast<u32*>(&t);
}
__device__ __forceinline__ void split4(float4 v, u32& h0, u32& h1, u32& l0, u32& l1) {
    __nv_bfloat16 hx = __float2bfloat16(v.x), hy = __float2bfloat16(v.y);
    __nv_bfloat16 hz = __float2bfloat16(v.z), hw = __float2bfloat16(v.w);
    h0 = bf16pair(__bfloat162float(hx), __bfloat162float(hy));
    h1 = bf16pair(__bfloat162float(hz), __bfloat162float(hw));
    l0 = bf16pair(v.x - __bfloat162float(hx), v.y - __bfloat162float(hy));
    l1 = bf16pair(v.z - __bfloat162float(hz), v.w - __bfloat162float(hw));
}
__device__ __forceinline__ void mma16816(float* c, const u32* a, const u32* b) {
    asm volatile(
        "mma.sync.aligned.m16n8k16.row.col.f32.bf16.bf16.f32 "
        "{%0,%1,%2,%3}, {%4,%5,%6,%7}, {%8,%9}, {%0,%1,%2,%3};"
        : "+f"(c[0]), "+f"(c[1]), "+f"(c[2]), "+f"(c[3])
        : "r"(a[0]), "r"(a[1]), "r"(a[2]), "r"(a[3]), "r"(b[0]), "r"(b[1]));
}

// smem layout (bytes) for the fused MLP kernel
#define SM_AH 0
#define SM_AL (HIDC * ROWB)
#define SM_W1H (2 * HIDC * ROWB)
#define SM_W1L (3 * HIDC * ROWB)
#define SM_W2H (4 * HIDC * ROWB)
#define SM_W2L (5 * HIDC * ROWB)
#define SM_BIAS (6 * HIDC * ROWB)
#define SM_TOT (6 * HIDC * ROWB + 512)   // ~204.9 KB

// ---------------------------------------------------------------------------
// k_prep: hi/lo split weights into padded [o][k] layout; also zero g_cnt
// ---------------------------------------------------------------------------
__global__ void k_prep(const float* __restrict__ W1l, const float* __restrict__ W1r,
                       const float* __restrict__ W2l, const float* __restrict__ W2r,
                       int n) {
    int stride = gridDim.x * blockDim.x;
    int tid0 = blockIdx.x * blockDim.x + threadIdx.x;
    for (int i = tid0; i < HIDC * HIDC; i += stride) {
        int o = i >> 7, k = i & 127;
        float wc = (k < 64) ? W1l[o * 64 + k] : W1r[o * 64 + (k - 64)];
        float wz = (o < 64) ? W2l[o * 128 + k] : W2r[(o - 64) * 128 + k];
        int off = o * SBF + k;
        __nv_bfloat16 ch = __float2bfloat16(wc);
        __nv_bfloat16 zh = __float2bfloat16(wz);
        g_Wc_hi[off] = ch;
        g_Wc_lo[off] = __float2bfloat16(wc - __bfloat162float(ch));
        g_Wz_hi[off] = zh;
        g_Wz_lo[off] = __float2bfloat16(wz - __bfloat162float(zh));
    }
    for (int i = tid0; i < n; i += stride) g_cnt[i] = 0;
}

// ---------------------------------------------------------------------------
// CSR build: hist -> scan -> reorder
// ---------------------------------------------------------------------------
__global__ void k_hist(const int* __restrict__ dst, int E) {
    for (int e = blockIdx.x * blockDim.x + threadIdx.x; e < E; e += gridDim.x * blockDim.x)
        atomicAdd(&g_cnt[dst[e]], 1);
}
__global__ void k_scan1(int n) {
    __shared__ int s[1024];
    int t = threadIdx.x;
    int i = blockIdx.x * 1024 + t;
    int v = (i < n) ? g_cnt[i] : 0;
    s[t] = v;
    __syncthreads();
    #pragma unroll
    for (int o = 1; o < 1024; o <<= 1) {
        int tmp = (t >= o) ? s[t - o] : 0;
        __syncthreads();
        s[t] += tmp;
        __syncthreads();
    }
    if (i < n) g_off[i] = s[t] - v;        // exclusive
    if (t == 1023) g_bsum[blockIdx.x] = s[t];
}
__global__ void k_scan2(int nb) {
    if (threadIdx.x == 0) {
        int run = 0;
        for (int b = 0; b < nb; b++) { int v = g_bsum[b]; g_bsum[b] = run; run += v; }
    }
}
__global__ void k_scan3(int n) {
    for (int i = blockIdx.x * blockDim.x + threadIdx.x; i < n; i += gridDim.x * blockDim.x) {
        int o = g_off[i] + g_bsum[i >> 10];
        g_off[i] = o;
        g_cur[i] = o;
    }
}
__global__ void k_reorder(const int* __restrict__ src, const int* __restrict__ dst, int E) {
    for (int e = blockIdx.x * blockDim.x + threadIdx.x; e < E; e += gridDim.x * blockDim.x) {
        int pos = atomicAdd(&g_cur[dst[e]], 1);
        g_ssrc[pos] = src[e];
    }
}

// ---------------------------------------------------------------------------
// k_gather1: agg1m[d] = mean_{s in N(d)} x[s]   (16 threads per dst, float4 each)
// ---------------------------------------------------------------------------
__global__ void __launch_bounds__(256) k_gather1(const float4* __restrict__ x4, int n) {
    int d = blockIdx.x * 16 + (threadIdx.x >> 4);
    int p = threadIdx.x & 15;
    if (d >= n) return;
    int off = g_off[d];
    int cnt = g_cnt[d];
    int end = off + cnt;
    float4 a0 = make_float4(0.f, 0.f, 0.f, 0.f);
    float4 a1 = make_float4(0.f, 0.f, 0.f, 0.f);
    int j = off;
    for (; j + 1 < end; j += 2) {
        int s0 = g_ssrc[j], s1 = g_ssrc[j + 1];
        float4 v0 = x4[(long)s0 * 16 + p];
        float4 v1 = x4[(long)s1 * 16 + p];
        a0.x += v0.x; a0.y += v0.y; a0.z += v0.z; a0.w += v0.w;
        a1.x += v1.x; a1.y += v1.y; a1.z += v1.z; a1.w += v1.w;
    }
    if (j < end) {
        float4 v = x4[(long)g_ssrc[j] * 16 + p];
        a0.x += v.x; a0.y += v.y; a0.z += v.z; a0.w += v.w;
    }
    float inv = 1.0f / fmaxf((float)cnt, 1.0f);
    float4 o = make_float4((a0.x + a1.x) * inv, (a0.y + a1.y) * inv,
                           (a0.z + a1.z) * inv, (a0.w + a1.w) * inv);
    ((float4*)g_agg1m)[(long)d * 16 + p] = o;
}

// ---------------------------------------------------------------------------
// k_gather2_out: out[d] = sigmoid( r[d] + b2 + mean_{s in N(d)} z[s] )
// ---------------------------------------------------------------------------
__global__ void __launch_bounds__(256) k_gather2_out(
    const float* __restrict__ b2, float* __restrict__ out, int n) {
    int d = blockIdx.x * 16 + (threadIdx.x >> 4);
    int p = threadIdx.x & 15;
    if (d >= n) return;
    int off = g_off[d];
    int cnt = g_cnt[d];
    int end = off + cnt;
    const float4* z4 = (const float4*)g_z;
    float4 a0 = make_float4(0.f, 0.f, 0.f, 0.f);
    float4 a1 = make_float4(0.f, 0.f, 0.f, 0.f);
    int j = off;
    for (; j + 1 < end; j += 2) {
        int s0 = g_ssrc[j], s1 = g_ssrc[j + 1];
        float4 v0 = z4[(long)s0 * 16 + p];
        float4 v1 = z4[(long)s1 * 16 + p];
        a0.x += v0.x; a0.y += v0.y; a0.z += v0.z; a0.w += v0.w;
        a1.x += v1.x; a1.y += v1.y; a1.z += v1.z; a1.w += v1.w;
    }
    if (j < end) {
        float4 v = z4[(long)g_ssrc[j] * 16 + p];
        a0.x += v.x; a0.y += v.y; a0.z += v.z; a0.w += v.w;
    }
    float inv = 1.0f / fmaxf((float)cnt, 1.0f);
    float4 rr = ((const float4*)g_r)[(long)d * 16 + p];
    float4 bb = *(const float4*)(b2 + p * 4);
    float s0 = rr.x + bb.x + (a0.x + a1.x) * inv;
    float s1 = rr.y + bb.y + (a0.y + a1.y) * inv;
    float s2 = rr.z + bb.z + (a0.z + a1.z) * inv;
    float s3 = rr.w + bb.w + (a0.w + a1.w) * inv;
    float4 o;
    o.x = 1.0f / (1.0f + __expf(-s0));
    o.y = 1.0f / (1.0f + __expf(-s1));
    o.z = 1.0f / (1.0f + __expf(-s2));
    o.w = 1.0f / (1.0f + __expf(-s3));
    ((float4*)out)[(long)d * 16 + p] = o;
}

// ---------------------------------------------------------------------------
// GEMM mainloop: warp tile 32m x 32n (2 mi x 4 ni) — light register footprint
// ---------------------------------------------------------------------------
__device__ __forceinline__ void gemm_mainloop(const char* smc, int wbase,
                                              int mt, int ng, int lane,
                                              float acc[2][4][4]) {
    int g = lane >> 2;
    int t = lane & 3;
    const char* arow0 = smc + SM_AH + (mt * 32 + g) * ROWB;
    const char* wrow0 = smc + wbase + (ng * 32 + g) * ROWB;
    const ptrdiff_t LO = SM_AL - SM_AH;   // hi->lo delta (same for W regions)

    #pragma unroll
    for (int ks = 0; ks < 8; ks++) {
        int kb = (ks * 16 + 2 * t) * 2;
        u32 ah[2][4], al[2][4], wh[4][2], wl[4][2];
        #pragma unroll
        for (int mi = 0; mi < 2; mi++) {
            const char* rp = arow0 + mi * 16 * ROWB;
            ah[mi][0] = *(const u32*)(rp + kb);
            ah[mi][1] = *(const u32*)(rp + 8 * ROWB + kb);
            ah[mi][2] = *(const u32*)(rp + kb + 16);
            ah[mi][3] = *(const u32*)(rp + 8 * ROWB + kb + 16);
            al[mi][0] = *(const u32*)(rp + LO + kb);
            al[mi][1] = *(const u32*)(rp + LO + 8 * ROWB + kb);
            al[mi][2] = *(const u32*)(rp + LO + kb + 16);
            al[mi][3] = *(const u32*)(rp + LO + 8 * ROWB + kb + 16);
        }
        #pragma unroll
        for (int ni = 0; ni < 4; ni++) {
            const char* wp = wrow0 + ni * 8 * ROWB;
            wh[ni][0] = *(const u32*)(wp + kb);
            wh[ni][1] = *(const u32*)(wp + kb + 16);
            wl[ni][0] = *(const u32*)(wp + LO + kb);
            wl[ni][1] = *(const u32*)(wp + LO + kb + 16);
        }
        #pragma unroll
        for (int ni = 0; ni < 4; ni++) {
            #pragma unroll
            for (int mi = 0; mi < 2; mi++) {
                mma16816(acc[mi][ni], ah[mi], wh[ni]);
                mma16816(acc[mi][ni], ah[mi], wl[ni]);
                mma16816(acc[mi][ni], al[mi], wh[ni]);
            }
        }
    }
}

// ---------------------------------------------------------------------------
// k_mlp_fused (512 thr, 16 warps, 128-node tile):
//   h = relu([agg1m, x] @ W1^T + b1)   (h stays in smem, split hi/lo)
//   [z|r] = h @ Wzr^T -> g_z / g_r
// Warp w: m rows [(w>>2)*32, +32), n cols [(w&3)*32, +32)
// ---------------------------------------------------------------------------
__global__ void __launch_bounds__(512) k_mlp_fused(
    const float* __restrict__ x, const float* __restrict__ b1, int n) {
    extern __shared__ char smc[];
    int tid = threadIdx.x;
    int warp = tid >> 5;
    int lane = tid & 31;
    int base = blockIdx.x * TMT;
    int mt = warp >> 2;
    int ng = warp & 3;
    int g = lane >> 2;
    int t = lane & 3;

    // stage both weight sets (flat copies)
    for (int i = tid; i < HIDC * ROWB / 16; i += 512) {
        ((float4*)(smc + SM_W1H))[i] = ((const float4*)g_Wc_hi)[i];
        ((float4*)(smc + SM_W1L))[i] = ((const float4*)g_Wc_lo)[i];
        ((float4*)(smc + SM_W2H))[i] = ((const float4*)g_Wz_hi)[i];
        ((float4*)(smc + SM_W2L))[i] = ((const float4*)g_Wz_lo)[i];
    }
    if (tid < HIDC) ((float*)(smc + SM_BIAS))[tid] = b1[tid];

    // stage A1: row m = tid>>2; quarter q4 = tid&3 covers 32 cols
    {
        int m = tid >> 2;
        int q4 = tid & 3;
        int node = base + m;
        char* rowh = smc + SM_AH + m * ROWB + q4 * 64;
        char* rowl = smc + SM_AL + m * ROWB + q4 * 64;
        #pragma unroll
        for (int j = 0; j < 8; j++) {
            int c = q4 * 32 + j * 4;     // 0..127
            float4 v = make_float4(0.f, 0.f, 0.f, 0.f);
            if (node < n) {
                v = (c < 64)
                    ? *(const float4*)(g_agg1m + (long)node * INC + c)
                    : *(const float4*)(x + (long)node * INC + (c - 64));
            }
            u32 h0, h1, l0, l1;
            split4(v, h0, h1, l0, l1);
            *(uint2*)(rowh + j * 8) = make_uint2(h0, h1);
            *(uint2*)(rowl + j * 8) = make_uint2(l0, l1);
        }
    }
    __syncthreads();

    float acc[2][4][4];
    #pragma unroll
    for (int a = 0; a < 2; a++)
        #pragma unroll
        for (int b = 0; b < 4; b++)
            #pragma unroll
            for (int c = 0; c < 4; c++) acc[a][b][c] = 0.f;

    // ---- GEMM1 ----
    gemm_mainloop(smc, SM_W1H, mt, ng, lane, acc);
    __syncthreads();   // all warps done reading A1 before overwrite

    // epilogue1: bias + relu, split h hi/lo back into A buffers
    {
        const float* bias = (const float*)(smc + SM_BIAS);
        #pragma unroll
        for (int ni = 0; ni < 4; ni++) {
            int c = ng * 32 + ni * 8 + 2 * t;
            float b0v = bias[c], b1v = bias[c + 1];
            #pragma unroll
            for (int mi = 0; mi < 2; mi++) {
                #pragma unroll
                for (int rr = 0; rr < 2; rr++) {
                    int r = mt * 32 + mi * 16 + rr * 8 + g;
                    float v0 = fmaxf(acc[mi][ni][rr * 2 + 0] + b0v, 0.f);
                    float v1 = fmaxf(acc[mi][ni][rr * 2 + 1] + b1v, 0.f);
                    __nv_bfloat16 h0 = __float2bfloat16(v0);
                    __nv_bfloat16 h1 = __float2bfloat16(v1);
                    u32 hp = bf16pair(__bfloat162float(h0), __bfloat162float(h1));
                    u32 lp = bf16pair(v0 - __bfloat162float(h0), v1 - __bfloat162float(h1));
                    *(u32*)(smc + SM_AH + r * ROWB + c * 2) = hp;
                    *(u32*)(smc + SM_AL + r * ROWB + c * 2) = lp;
                }
            }
        }
    }
    __syncthreads();

    #pragma unroll
    for (int a = 0; a < 2; a++)
        #pragma unroll
        for (int b = 0; b < 4; b++)
            #pragma unroll
            for (int c = 0; c < 4; c++) acc[a][b][c] = 0.f;

    // ---- GEMM2 ----
    gemm_mainloop(smc, SM_W2H, mt, ng, lane, acc);

    // epilogue2: ng<2 -> g_z cols ng*32.., ng>=2 -> g_r cols (ng-2)*32..
    {
        float* dstp = (ng < 2) ? g_z : g_r;
        int nb = ng & 1;
        #pragma unroll
        for (int ni = 0; ni < 4; ni++) {
            int oc = nb * 32 + ni * 8 + 2 * t;
            #pragma unroll
            for (int mi = 0; mi < 2; mi++) {
                int r0 = base + mt * 32 + mi * 16 + g;
                if (r0 < n)
                    *(float2*)(dstp + (long)r0 * OUTC + oc) =
                        make_float2(acc[mi][ni][0], acc[mi][ni][1]);
                int r1 = r0 + 8;
                if (r1 < n)
                    *(float2*)(dstp + (long)r1 * OUTC + oc) =
                        make_float2(acc[mi][ni][2], acc[mi][ni][3]);
            }
        }
    }
}

// ---------------------------------------------------------------------------
// kernel_launch  (inputs: x, edge_index, W1_l, W1_r, b1, W2_l, W2_r, b2)
// ---------------------------------------------------------------------------
extern "C" void kernel_launch(void* const* d_in, const int* in_sizes, int n_in,
                              void* d_out, int out_size) {
    const float* x   = (const float*)d_in[0];
    const int*   ei  = (const int*)d_in[1];
    const float* W1l = (const float*)d_in[2];
    const float* W1r = (const float*)d_in[3];
    const float* b1  = (const float*)d_in[4];
    const float* W2l = (const float*)d_in[5];
    const float* W2r = (const float*)d_in[6];
    const float* b2  = (const float*)d_in[7];
    float* out = (float*)d_out;

    int n = in_sizes[0] / INC;
    int E = in_sizes[1] / 2;
    const int* src = ei;
    const int* dst = ei + E;

    cudaFuncSetAttribute(k_mlp_fused, cudaFuncAttributeMaxDynamicSharedMemorySize, SM_TOT);

    int nt = (n + TMT - 1) / TMT;
    int nb = (n + 1023) / 1024;

    // weights split + cnt zero
    k_prep<<<128, 256>>>(W1l, W1r, W2l, W2r, n);

    // --- CSR build ---
    k_hist<<<1024, 256>>>(dst, E);
    k_scan1<<<nb, 1024>>>(n);
    k_scan2<<<1, 32>>>(nb);
    k_scan3<<<(n + 255) / 256, 256>>>(n);
    k_reorder<<<1024, 256>>>(src, dst, E);

    // --- layer 1 aggregate + fused dense ---
    k_gather1<<<(n + 15) / 16, 256>>>((const float4*)x, n);
    k_mlp_fused<<<nt, 512, SM_TOT>>>(x, b1, n);

    // --- layer 2 aggregate fused with output ---
    k_gather2_out<<<(n + 15) / 16, 256>>>(b2, out, n);
}